// round 13
// baseline (speedup 1.0000x reference)
#include <cuda_runtime.h>
#include <cuda_fp16.h>
#include <math.h>
#include <float.h>
#include <stdint.h>

// ---------------- problem constants ----------------
#define NTOK   8192          // B*R*C tokens = 2*1024*4
#define EDIM   256
#define SPLIT  768
#define TOPK_  32
#define LATD   128
#define MLPD   1024

// ---------------- device scratch (no allocs allowed) ----------------
__device__ float g_QKV[NTOK*768];    // also reused as split-K partial buffers later
__device__ float g_X  [NTOK*EDIM];
__device__ float g_ST [NTOK*EDIM];
__device__ float g_IQK[NTOK*64];
__device__ float g_SC [3*32];
__device__ int   g_QI [NTOK*8];
__device__ int   g_KI [NTOK*8];
__device__ int   g_IDX[NTOK*TOPK_];
__device__ float g_MQ [NTOK*EDIM];
__device__ float g_KV [NTOK*2*EDIM];
__device__ float g_ST2[NTOK*EDIM];
__device__ float g_X2 [NTOK*EDIM];
__device__ float g_X3 [NTOK*EDIM];
// fp16 split buffers (A-side hi/lo; W single fp16)
__device__ __half g_SRCh[NTOK*EDIM],  g_SRCl[NTOK*EDIM];
__device__ __half g_AOh [NTOK*EDIM],  g_AOl [NTOK*EDIM];
__device__ __half g_STh [NTOK*EDIM],  g_STl [NTOK*EDIM];
__device__ __half g_CDh [NTOK*LATD],  g_CDl [NTOK*LATD];
__device__ __half g_AO2h[NTOK*EDIM],  g_AO2l[NTOK*EDIM];
__device__ __half g_X2h [NTOK*EDIM],  g_X2l [NTOK*EDIM];
__device__ __half g_H1h [NTOK*MLPD],  g_H1l [NTOK*MLPD];
__device__ __half g_W   [1<<20];

// weight offsets inside g_W (idx rows packed right after MD for merged N=448 GEMM)
#define W_FAIN  0
#define W_FAOUT 196608
#define W_MQ    262144
#define W_MD    327680
#define W_IDX   360448
#define W_MU    376832
#define W_MO    442368
#define W_L1    507904
#define W_L2    770048

// ---------------- helpers ----------------
__device__ __forceinline__ uint32_t s2u(const void* p) {
    uint32_t a;
    asm("{ .reg .u64 t; cvta.to.shared.u64 t, %1; cvt.u32.u64 %0, t; }" : "=r"(a) : "l"(p));
    return a;
}
__device__ __forceinline__ void ldsm4(uint32_t* r, uint32_t addr) {
    asm volatile("ldmatrix.sync.aligned.m8n8.x4.shared.b16 {%0,%1,%2,%3}, [%4];"
                 : "=r"(r[0]), "=r"(r[1]), "=r"(r[2]), "=r"(r[3]) : "r"(addr));
}
__device__ __forceinline__ void mma16816(float* d, const uint32_t* a, const uint32_t* b) {
    asm volatile("mma.sync.aligned.m16n8k16.row.col.f32.f16.f16.f32 "
                 "{%0,%1,%2,%3}, {%4,%5,%6,%7}, {%8,%9}, {%0,%1,%2,%3};"
                 : "+f"(d[0]), "+f"(d[1]), "+f"(d[2]), "+f"(d[3])
                 : "r"(a[0]), "r"(a[1]), "r"(a[2]), "r"(a[3]), "r"(b[0]), "r"(b[1]));
}
#define CPA(dst, src) asm volatile("cp.async.cg.shared.global [%0], [%1], 16;" :: "r"(dst), "l"(src))
#define CPA_COMMIT()  asm volatile("cp.async.commit_group;" ::: "memory")
#define CPA_WAIT1()   asm volatile("cp.async.wait_group 1;" ::: "memory")
#define CPA_WAIT0()   asm volatile("cp.async.wait_group 0;" ::: "memory")

__device__ __forceinline__ __half2 split_hi(float a, float b, __half2& lo) {
    __half2 hi;
    hi.x = __float2half_rn(a); hi.y = __float2half_rn(b);
    lo.x = __float2half_rn(a - __half2float(hi.x));
    lo.y = __float2half_rn(b - __half2float(hi.y));
    return hi;
}
__device__ __forceinline__ void cvt4(const float* __restrict__ x, __half* __restrict__ hi,
                                     __half* __restrict__ lo, int i) {
    float4 v = *reinterpret_cast<const float4*>(x + i);
    __half2 l0, l1;
    __half2 h0 = split_hi(v.x, v.y, l0);
    __half2 h1 = split_hi(v.z, v.w, l1);
    *reinterpret_cast<__half2*>(hi + i)     = h0;
    *reinterpret_cast<__half2*>(hi + i + 2) = h1;
    *reinterpret_cast<__half2*>(lo + i)     = l0;
    *reinterpret_cast<__half2*>(lo + i + 2) = l1;
}
__device__ __forceinline__ void cvt4w(const float* __restrict__ x, __half* __restrict__ w, int i) {
    float4 v = *reinterpret_cast<const float4*>(x + i);
    __half2 h0; h0.x = __float2half_rn(v.x); h0.y = __float2half_rn(v.y);
    __half2 h1; h1.x = __float2half_rn(v.z); h1.y = __float2half_rn(v.w);
    *reinterpret_cast<__half2*>(w + i)     = h0;
    *reinterpret_cast<__half2*>(w + i + 2) = h1;
}

// ---------------- conversions ----------------
__global__ void cvt_split(const float* __restrict__ x, __half* __restrict__ hi,
                          __half* __restrict__ lo, int n) {
    int i = (blockIdx.x * 256 + threadIdx.x) * 4;
    if (i < n) cvt4(x, hi, lo, i);
}

__global__ void wcvt_fa(const float* __restrict__ fin, const float* __restrict__ fout,
                        __half* __restrict__ W) {
    int b = blockIdx.x;
    const float* src; int dst, rel;
    if (b < 192) { src = fin;  dst = W_FAIN;  rel = b; }
    else         { src = fout; dst = W_FAOUT; rel = b - 192; }
    int i = (rel*256 + threadIdx.x)*4;
    cvt4w(src, W + dst, i);
}

__global__ void wcvt6(const float* __restrict__ mq, const float* __restrict__ md,
                      const float* __restrict__ mu, const float* __restrict__ mo,
                      const float* __restrict__ l1, const float* __restrict__ l2,
                      const float* __restrict__ iq, const float* __restrict__ ik,
                      __half* __restrict__ W) {
    int b = blockIdx.x;
    const float* src; int dst, rel;
    if (b < 64)       { src = mq; dst = W_MQ;        rel = b; }
    else if (b < 96)  { src = md; dst = W_MD;        rel = b-64; }
    else if (b < 104) { src = iq; dst = W_IDX;       rel = b-96; }
    else if (b < 112) { src = ik; dst = W_IDX+8192;  rel = b-104; }
    else if (b < 176) { src = mu; dst = W_MU;        rel = b-112; }
    else if (b < 240) { src = mo; dst = W_MO;        rel = b-176; }
    else if (b < 496) { src = l1; dst = W_L1;        rel = b-240; }
    else              { src = l2; dst = W_L2;        rel = b-496; }
    int i = (rel*256 + threadIdx.x)*4;
    cvt4w(src, W + dst, i);
}

// ---------------- HMMA fp16 2-term GEMM, BM=128, BN=64, 3 CTA/SM, optional split-K ----
// D = Ah*W + Al*W.
// EPI: 0 +bias(opt); 1 +bias(opt)+res; 2 gelu(acc+bias) split-out; 3 MQ/CD/IQK mixed
// KS: split-K factor (blockIdx.z). kz>0 CTAs write raw partials to part[(kz-1)*M*N + ...].
#define PADH 40   // halves per smem row (80B stride)
#define STAGE 25600   // 20480 (A hi+lo) + 5120 (B)

template<int EPI, int OSPLIT, int KS>
__global__ void __launch_bounds__(256, 3)
hgemm(const __half* __restrict__ Ahi, const __half* __restrict__ Alo,
      const __half* __restrict__ W,
      const float* __restrict__ bias, const float* __restrict__ res,
      float* __restrict__ C, __half* __restrict__ Chi, __half* __restrict__ Clo,
      float* __restrict__ C2,
      int M, int N, int K) {
    constexpr int WNT  = 32;
    constexpr int NPI  = 2;
    constexpr int NNI  = 4;

    extern __shared__ __align__(16) char smem[];
    const uint32_t sb = s2u(smem);
    const int tid  = threadIdx.x;
    const int warp = tid >> 5, lane = tid & 31;
    const int wm = warp & 3, wn = warp >> 2;
    const int bm = blockIdx.y * 128, bn = blockIdx.x * 64;
    const int kz = (KS > 1) ? blockIdx.z : 0;
    const int Kc = K / KS;               // K per split
    const int kbase = kz * Kc;

    float acc[2][NNI][4];
    #pragma unroll
    for (int i = 0; i < 2; i++)
        #pragma unroll
        for (int j = 0; j < NNI; j++)
            #pragma unroll
            for (int l = 0; l < 4; l++) acc[i][j][l] = 0.0f;

    const int a_r = (lane & 7) + ((lane >> 3) & 1) * 8;
    const int a_c = ((lane >> 4) & 1) * 8;
    const int b_r = (lane & 7) + ((lane >> 4) & 1) * 8;
    const int b_c = ((lane >> 3) & 1) * 8;

    const int nch = Kc >> 5;

    auto load_stage = [&](int st, int k0) {
        uint32_t base = sb + st*STAGE;
        #pragma unroll
        for (int c = tid; c < 512; c += 256) {
            int row = c >> 2, seg = c & 3;
            uint32_t d = base + row*80 + seg*16;
            CPA(d,         Ahi + (size_t)(bm + row)*K + kbase + k0 + seg*8);
            CPA(d + 10240, Alo + (size_t)(bm + row)*K + kbase + k0 + seg*8);
        }
        {
            int row = tid >> 2, seg = tid & 3;
            uint32_t d = base + 20480 + row*80 + seg*16;
            CPA(d, W + (size_t)(bn + row)*K + kbase + k0 + seg*8);
        }
        CPA_COMMIT();
    };

    load_stage(0, 0);

    for (int c = 0; c < nch; c++) {
        if (c + 1 < nch) { load_stage((c+1) & 1, (c+1) << 5); CPA_WAIT1(); }
        else             { CPA_WAIT0(); }
        __syncthreads();

        const uint32_t base = sb + (c & 1)*STAGE;
        #pragma unroll
        for (int ks = 0; ks < 2; ks++) {
            uint32_t ah[2][4], al[2][4];
            #pragma unroll
            for (int mi = 0; mi < 2; mi++) {
                uint32_t off = base + ((wm*32 + mi*16 + a_r)*PADH + ks*16 + a_c) * 2;
                ldsm4(ah[mi], off);
                ldsm4(al[mi], off + 10240);
            }
            uint32_t bh[NNI][2];
            #pragma unroll
            for (int pi = 0; pi < NPI; pi++) {
                uint32_t off = base + 20480 + ((wn*WNT + pi*16 + b_r)*PADH + ks*16 + b_c) * 2;
                uint32_t t[4];
                ldsm4(t, off);
                bh[2*pi][0]=t[0]; bh[2*pi][1]=t[1]; bh[2*pi+1][0]=t[2]; bh[2*pi+1][1]=t[3];
            }
            #pragma unroll
            for (int ni = 0; ni < NNI; ni++)
                #pragma unroll
                for (int mi = 0; mi < 2; mi++) {
                    mma16816(acc[mi][ni], ah[mi], bh[ni]);
                    mma16816(acc[mi][ni], al[mi], bh[ni]);
                }
        }
        __syncthreads();
    }

    const int gr = lane >> 2, gc = (lane & 3) * 2;
    #pragma unroll
    for (int mi = 0; mi < 2; mi++) {
        #pragma unroll
        for (int ni = 0; ni < NNI; ni++) {
            int r0 = bm + wm*32 + mi*16 + gr;
            int cc = bn + wn*WNT + ni*8 + gc;
            float2 v0 = make_float2(acc[mi][ni][0], acc[mi][ni][1]);
            float2 v1 = make_float2(acc[mi][ni][2], acc[mi][ni][3]);
            if (KS > 1 && kz > 0) {
                // raw partial, no bias/res
                float* P = C2 + ((size_t)(kz-1)*M + r0)*N + cc;
                *reinterpret_cast<float2*>(P)               = v0;
                *reinterpret_cast<float2*>(P + (size_t)8*N) = v1;
                continue;
            }
            if (EPI != 3 && bias) {
                float2 bz = *reinterpret_cast<const float2*>(bias + cc);
                v0.x += bz.x; v0.y += bz.y; v1.x += bz.x; v1.y += bz.y;
            }
            if (EPI == 1) {
                float2 r0v = *reinterpret_cast<const float2*>(res + (size_t)r0*N + cc);
                float2 r1v = *reinterpret_cast<const float2*>(res + (size_t)(r0+8)*N + cc);
                v0.x += r0v.x; v0.y += r0v.y; v1.x += r1v.x; v1.y += r1v.y;
            }
            if (EPI == 2) {
                v0.x = 0.5f*v0.x*(1.0f + erff(v0.x*0.7071067811865475f));
                v0.y = 0.5f*v0.y*(1.0f + erff(v0.y*0.7071067811865475f));
                v1.x = 0.5f*v1.x*(1.0f + erff(v1.x*0.7071067811865475f));
                v1.y = 0.5f*v1.y*(1.0f + erff(v1.y*0.7071067811865475f));
            }
            if (EPI == 3) {
                if (cc < 256) {
                    *reinterpret_cast<float2*>(C + (size_t)r0*256 + cc)     = v0;
                    *reinterpret_cast<float2*>(C + (size_t)(r0+8)*256 + cc) = v1;
                } else if (cc < 384) {
                    int c2 = cc - 256;
                    __half2 l0, l1;
                    __half2 h0 = split_hi(v0.x, v0.y, l0);
                    __half2 h1 = split_hi(v1.x, v1.y, l1);
                    *reinterpret_cast<__half2*>(Chi + (size_t)r0*128 + c2)     = h0;
                    *reinterpret_cast<__half2*>(Clo + (size_t)r0*128 + c2)     = l0;
                    *reinterpret_cast<__half2*>(Chi + (size_t)(r0+8)*128 + c2) = h1;
                    *reinterpret_cast<__half2*>(Clo + (size_t)(r0+8)*128 + c2) = l1;
                } else {
                    int c2 = cc - 384;
                    *reinterpret_cast<float2*>(C2 + (size_t)r0*64 + c2)     = v0;
                    *reinterpret_cast<float2*>(C2 + (size_t)(r0+8)*64 + c2) = v1;
                }
            } else if (OSPLIT) {
                __half2 l0, l1;
                __half2 h0 = split_hi(v0.x, v0.y, l0);
                __half2 h1 = split_hi(v1.x, v1.y, l1);
                *reinterpret_cast<__half2*>(Chi + (size_t)r0*N + cc)     = h0;
                *reinterpret_cast<__half2*>(Clo + (size_t)r0*N + cc)     = l0;
                *reinterpret_cast<__half2*>(Chi + (size_t)(r0+8)*N + cc) = h1;
                *reinterpret_cast<__half2*>(Clo + (size_t)(r0+8)*N + cc) = l1;
            } else {
                *reinterpret_cast<float2*>(C + (size_t)r0*N + cc)     = v0;
                *reinterpret_cast<float2*>(C + (size_t)(r0+8)*N + cc) = v1;
            }
        }
    }
}

// ---------------- feature attention over C=4 tokens (fp16 split output) ----------------
__global__ void feat_attn(const float* __restrict__ QKV,
                          __half* __restrict__ AOh, __half* __restrict__ AOl) {
    int s = blockIdx.x;
    int h = threadIdx.x >> 5;
    int lane = threadIdx.x & 31;
    float q[4], k[4], v[4];
    #pragma unroll
    for (int c = 0; c < 4; c++) {
        const float* row = QKV + (size_t)(s*4 + c) * 768;
        q[c] = row[h*32 + lane];
        k[c] = row[256 + h*32 + lane];
        v[c] = row[512 + h*32 + lane];
    }
    float sc[4][4];
    #pragma unroll
    for (int a = 0; a < 4; a++)
        #pragma unroll
        for (int b = 0; b < 4; b++) {
            float p = q[a] * k[b];
            #pragma unroll
            for (int o = 16; o > 0; o >>= 1) p += __shfl_xor_sync(0xffffffffu, p, o);
            sc[a][b] = p * 0.17677669529663687f;
        }
    #pragma unroll
    for (int a = 0; a < 4; a++) {
        float mx = fmaxf(fmaxf(sc[a][0], sc[a][1]), fmaxf(sc[a][2], sc[a][3]));
        float e0 = expf(sc[a][0]-mx), e1 = expf(sc[a][1]-mx);
        float e2 = expf(sc[a][2]-mx), e3 = expf(sc[a][3]-mx);
        float den = e0 + e1 + e2 + e3;
        float o = (e0*v[0] + e1*v[1] + e2*v[2] + e3*v[3]) / den;
        __half oh = __float2half_rn(o);
        __half ol = __float2half_rn(o - __half2float(oh));
        size_t idx = (size_t)(s*4 + a)*256 + h*32 + lane;
        AOh[idx] = oh;
        AOl[idx] = ol;
    }
}

// ---------------- layernorm, warp-per-token, layout remap, partial-sum inputs ----------------
__global__ void ln_kernel(const float* __restrict__ X,
                          const float* __restrict__ P1, const float* __restrict__ P2,
                          const float* __restrict__ P3,
                          const float* __restrict__ g, const float* __restrict__ b,
                          float* __restrict__ Y,
                          __half* __restrict__ Yhi, __half* __restrict__ Ylo, int mode) {
    int t = blockIdx.x * 8 + (threadIdx.x >> 5);
    int lane = threadIdx.x & 31;
    size_t off = (size_t)t * 256 + lane * 8;
    float4 x0 = *reinterpret_cast<const float4*>(X + off);
    float4 x1 = *reinterpret_cast<const float4*>(X + off + 4);
    if (P1) {
        float4 p0 = *reinterpret_cast<const float4*>(P1 + off);
        float4 p1 = *reinterpret_cast<const float4*>(P1 + off + 4);
        x0.x+=p0.x; x0.y+=p0.y; x0.z+=p0.z; x0.w+=p0.w;
        x1.x+=p1.x; x1.y+=p1.y; x1.z+=p1.z; x1.w+=p1.w;
    }
    if (P2) {
        float4 p0 = *reinterpret_cast<const float4*>(P2 + off);
        float4 p1 = *reinterpret_cast<const float4*>(P2 + off + 4);
        x0.x+=p0.x; x0.y+=p0.y; x0.z+=p0.z; x0.w+=p0.w;
        x1.x+=p1.x; x1.y+=p1.y; x1.z+=p1.z; x1.w+=p1.w;
    }
    if (P3) {
        float4 p0 = *reinterpret_cast<const float4*>(P3 + off);
        float4 p1 = *reinterpret_cast<const float4*>(P3 + off + 4);
        x0.x+=p0.x; x0.y+=p0.y; x0.z+=p0.z; x0.w+=p0.w;
        x1.x+=p1.x; x1.y+=p1.y; x1.z+=p1.z; x1.w+=p1.w;
    }
    float s = x0.x + x0.y + x0.z + x0.w + x1.x + x1.y + x1.z + x1.w;
    #pragma unroll
    for (int o = 16; o > 0; o >>= 1) s += __shfl_xor_sync(0xffffffffu, s, o);
    float m = s * (1.0f / 256.0f);
    float d[8] = {x0.x-m, x0.y-m, x0.z-m, x0.w-m, x1.x-m, x1.y-m, x1.z-m, x1.w-m};
    float vs = 0.f;
    #pragma unroll
    for (int i = 0; i < 8; i++) vs += d[i]*d[i];
    #pragma unroll
    for (int o = 16; o > 0; o >>= 1) vs += __shfl_xor_sync(0xffffffffu, vs, o);
    float inv = rsqrtf(vs * (1.0f/256.0f) + 1e-5f);
    float y[8];
    const float* gp = g + lane*8;
    const float* bp = b + lane*8;
    #pragma unroll
    for (int i = 0; i < 8; i++) y[i] = d[i]*inv*gp[i] + bp[i];
    int ot;
    if (mode == 0) ot = t;
    else if (mode == 1) { int bb = t >> 12, r = (t >> 2) & 1023, c = t & 3; ot = ((bb<<2)|c)*1024 + r; }
    else { int bf = t >> 10, r = t & 1023; int bb = bf >> 2, c = bf & 3; ot = bb*4096 + r*4 + c; }
    float* yr = Y + (size_t)ot * 256 + lane * 8;
    *reinterpret_cast<float4*>(yr)     = make_float4(y[0], y[1], y[2], y[3]);
    *reinterpret_cast<float4*>(yr + 4) = make_float4(y[4], y[5], y[6], y[7]);
    if (Yhi) {
        size_t o2 = (size_t)ot * 256 + lane * 8;
        #pragma unroll
        for (int i = 0; i < 4; i++) {
            __half2 lo;
            __half2 hi = split_hi(y[2*i], y[2*i+1], lo);
            *reinterpret_cast<__half2*>(Yhi + o2 + 2*i) = hi;
            *reinterpret_cast<__half2*>(Ylo + o2 + 2*i) = lo;
        }
    }
}

// ---------------- indexer: scales / quantize / score+topk ----------------
__global__ void idx_scales(const float* __restrict__ IQK, float* __restrict__ SC) {
    int bf = blockIdx.x, h = blockIdx.y, kind = blockIdx.z;
    int r0 = (kind == 1) ? SPLIT : 0;
    int r1 = (kind == 1) ? 1024 : SPLIT;
    int cb = (kind == 2) ? 32 : 0;
    int n = (r1 - r0) * 8;
    float m = 0.0f;
    for (int i = threadIdx.x; i < n; i += 256) {
        int r = r0 + (i >> 3), d = i & 7;
        m = fmaxf(m, fabsf(IQK[(size_t)(bf*1024 + r)*64 + cb + h*8 + d]));
    }
    __shared__ float sm[8];
    #pragma unroll
    for (int o = 16; o > 0; o >>= 1) m = fmaxf(m, __shfl_xor_sync(0xffffffffu, m, o));
    if ((threadIdx.x & 31) == 0) sm[threadIdx.x >> 5] = m;
    __syncthreads();
    if (threadIdx.x == 0) {
        float mm = sm[0];
        for (int i = 1; i < 8; i++) mm = fmaxf(mm, sm[i]);
        SC[kind*32 + bf*4 + h] = (mm + 1e-6f) / 127.0f;
    }
}

__global__ void idx_quant(const float* __restrict__ IQK, const float* __restrict__ SC,
                          int* __restrict__ QI, int* __restrict__ KI) {
    int idx = blockIdx.x * 256 + threadIdx.x;
    if (idx >= NTOK*32) return;
    int t = idx >> 5, j = idx & 31, h = j >> 3;
    int bf = t >> 10, r = t & 1023;
    char* qb = (char*)QI;
    char* kb = (char*)KI;
    float qs = SC[(r < SPLIT ? 0 : 1)*32 + bf*4 + h];
    float qv = rintf(IQK[(size_t)t*64 + j] / qs);
    qv = fminf(fmaxf(qv, -127.0f), 127.0f);
    qb[idx] = (char)(int)qv;
    if (r < SPLIT) {
        float ks = SC[64 + bf*4 + h];
        float kv = rintf(IQK[(size_t)t*64 + 32 + j] / ks);
        kv = fminf(fmaxf(kv, -127.0f), 127.0f);
        kb[idx] = (char)(int)kv;
    } else {
        kb[idx] = 0;
    }
}

// warp-per-token top-k: scores in 24 regs/lane, 32 argmax rounds, no block barriers
__global__ void idx_topk(const int* __restrict__ QI, const int* __restrict__ KI,
                         const float* __restrict__ SC, const float* __restrict__ ow,
                         int* __restrict__ IDX) {
    int warp = threadIdx.x >> 5, lane = threadIdx.x & 31;
    int t = blockIdx.x * 8 + warp;
    int bf = t >> 10, r = t & 1023;

    int4 q0 = *reinterpret_cast<const int4*>(QI + (size_t)t*8);
    int4 q1 = *reinterpret_cast<const int4*>(QI + (size_t)t*8 + 4);
    int qw[8] = {q0.x, q0.y, q0.z, q0.w, q1.x, q1.y, q1.z, q1.w};

    float ssc[4], sow[4];
    #pragma unroll
    for (int h = 0; h < 4; h++) {
        float qs = SC[(r < SPLIT ? 0 : 1)*32 + bf*4 + h];
        ssc[h] = qs * SC[64 + bf*4 + h];
        sow[h] = ow[h];
    }

    float rv[24];
    #pragma unroll
    for (int i = 0; i < 24; i++) {
        int k = i*32 + lane;
        const int* kw = KI + (size_t)(bf*1024 + k)*8;
        int4 k0 = *reinterpret_cast<const int4*>(kw);
        int4 k1 = *reinterpret_cast<const int4*>(kw + 4);
        int kwv[8] = {k0.x, k0.y, k0.z, k0.w, k1.x, k1.y, k1.z, k1.w};
        float acc = 0.f;
        #pragma unroll
        for (int h = 0; h < 4; h++) {
            int d = __dp4a(qw[2*h], kwv[2*h], __dp4a(qw[2*h+1], kwv[2*h+1], 0));
            acc += fmaxf((float)d * ssc[h], 0.0f) * sow[h];
        }
        rv[i] = acc;
    }

    for (int sel = 0; sel < TOPK_; sel++) {
        float bv = -FLT_MAX; int bi = 0x7fffffff;
        #pragma unroll
        for (int i = 0; i < 24; i++) {
            if (rv[i] > bv) { bv = rv[i]; bi = i*32 + lane; }
        }
        #pragma unroll
        for (int o = 16; o > 0; o >>= 1) {
            float ov = __shfl_xor_sync(0xffffffffu, bv, o);
            int   oi = __shfl_xor_sync(0xffffffffu, bi, o);
            if (ov > bv || (ov == bv && oi < bi)) { bv = ov; bi = oi; }
        }
        if (lane == 0) IDX[t*TOPK_ + sel] = bi;
        if ((bi & 31) == lane) rv[bi >> 5] = -FLT_MAX;
    }
}

// ---------------- sparse MLA attention v2: smem-staged, shuffle-light ----------------
__global__ void mla_attn(const float* __restrict__ MQ, const float* __restrict__ KV,
                         const int* __restrict__ IDX,
                         __half* __restrict__ AO2h, __half* __restrict__ AO2l) {
    __shared__ float sBuf[8][32][33];
    __shared__ float sQ[8][32];
    __shared__ float sW[8][32];
    __shared__ int sidx[32];

    int t = blockIdx.x;
    int bf = t >> 10;
    int h = threadIdx.x >> 5, lane = threadIdx.x & 31;

    if (threadIdx.x < 32) sidx[threadIdx.x] = IDX[t*TOPK_ + threadIdx.x];
    float q = MQ[(size_t)t*256 + h*32 + lane];
    sQ[h][lane] = q;
    __syncthreads();

    #pragma unroll 4
    for (int j = 0; j < 32; j++) {
        int kt = bf*1024 + sidx[j];
        sBuf[h][j][lane] = KV[(size_t)kt*512 + h*32 + lane];
    }
    __syncwarp();

    float score = 0.0f;
    #pragma unroll
    for (int d = 0; d < 32; d++)
        score += sQ[h][d] * sBuf[h][lane][d];
    score *= 0.17677669529663687f;

    float mx = score;
    #pragma unroll
    for (int o = 16; o > 0; o >>= 1) mx = fmaxf(mx, __shfl_xor_sync(0xffffffffu, mx, o));
    float e = expf(score - mx);
    float ssum = e;
    #pragma unroll
    for (int o = 16; o > 0; o >>= 1) ssum += __shfl_xor_sync(0xffffffffu, ssum, o);
    sW[h][lane] = e / ssum;
    __syncwarp();

    #pragma unroll 4
    for (int j = 0; j < 32; j++) {
        int kt = bf*1024 + sidx[j];
        sBuf[h][j][lane] = KV[(size_t)kt*512 + 256 + h*32 + lane];
    }
    __syncwarp();

    float acc = 0.0f;
    #pragma unroll
    for (int j = 0; j < 32; j++)
        acc += sW[h][j] * sBuf[h][j][lane];

    __half oh = __float2half_rn(acc);
    __half ol = __float2half_rn(acc - __half2float(oh));
    size_t idx = (size_t)t*256 + h*32 + lane;
    AO2h[idx] = oh;
    AO2l[idx] = ol;
}

// ---------------- host launcher ----------------
static float* symF(const void* sym) { void* p = nullptr; cudaGetSymbolAddress(&p, sym); return (float*)p; }
static int*   symI(const void* sym) { void* p = nullptr; cudaGetSymbolAddress(&p, sym); return (int*)p; }
static __half* symH(const void* sym) { void* p = nullptr; cudaGetSymbolAddress(&p, sym); return (__half*)p; }

extern "C" void kernel_launch(void* const* d_in, const int* in_sizes, int n_in,
                              void* d_out, int out_size) {
    (void)in_sizes; (void)n_in; (void)out_size;
    const float* src      = (const float*)d_in[0];
    const float* fa_in_w  = (const float*)d_in[2];
    const float* fa_in_b  = (const float*)d_in[3];
    const float* fa_out_w = (const float*)d_in[4];
    const float* fa_out_b = (const float*)d_in[5];
    const float* n1g = (const float*)d_in[6];
    const float* n1b = (const float*)d_in[7];
    const float* iqw = (const float*)d_in[8];
    const float* ikw = (const float*)d_in[9];
    const float* iow = (const float*)d_in[10];
    const float* mqw = (const float*)d_in[11];
    const float* mdw = (const float*)d_in[12];
    const float* muw = (const float*)d_in[13];
    const float* mow = (const float*)d_in[14];
    const float* n2g = (const float*)d_in[15];
    const float* n2b = (const float*)d_in[16];
    const float* l1w = (const float*)d_in[17];
    const float* l1b = (const float*)d_in[18];
    const float* l2w = (const float*)d_in[19];
    const float* l2b = (const float*)d_in[20];
    const float* n3g = (const float*)d_in[21];
    const float* n3b = (const float*)d_in[22];

    float* QKV = symF(g_QKV); float* X   = symF(g_X);   float* ST  = symF(g_ST);
    float* IQK = symF(g_IQK); float* SC  = symF(g_SC);
    int*   QI  = symI(g_QI);  int*   KI  = symI(g_KI);  int*   IDX = symI(g_IDX);
    float* MQ  = symF(g_MQ);  float* KV  = symF(g_KV);  float* ST2 = symF(g_ST2);
    float* X2  = symF(g_X2);  float* X3  = symF(g_X3);
    __half *SRCh=symH(g_SRCh), *SRCl=symH(g_SRCl);
    __half *AOh=symH(g_AOh),   *AOl=symH(g_AOl);
    __half *STh=symH(g_STh),   *STl=symH(g_STl);
    __half *CDh=symH(g_CDh),   *CDl=symH(g_CDl);
    __half *AO2h=symH(g_AO2h), *AO2l=symH(g_AO2l);
    __half *X2h=symH(g_X2h),   *X2l=symH(g_X2l);
    __half *H1h=symH(g_H1h),   *H1l=symH(g_H1l);
    __half *Wp=symH(g_W);
    float* PART = QKV;   // g_QKV reused as split-K partial space after feat_attn

    static cudaStream_t sW = nullptr, sB = nullptr;
    static cudaEvent_t evRoot = nullptr, evFA = nullptr, evW = nullptr, ev1 = nullptr, evB = nullptr;
    if (!sW) {
        cudaStreamCreateWithFlags(&sW, cudaStreamNonBlocking);
        cudaStreamCreateWithFlags(&sB, cudaStreamNonBlocking);
        cudaEventCreateWithFlags(&evRoot, cudaEventDisableTiming);
        cudaEventCreateWithFlags(&evFA,  cudaEventDisableTiming);
        cudaEventCreateWithFlags(&evW,   cudaEventDisableTiming);
        cudaEventCreateWithFlags(&ev1,   cudaEventDisableTiming);
        cudaEventCreateWithFlags(&evB,   cudaEventDisableTiming);
        cudaFuncSetAttribute(hgemm<0,0,1>, cudaFuncAttributeMaxDynamicSharedMemorySize, 51200);
        cudaFuncSetAttribute(hgemm<1,0,2>, cudaFuncAttributeMaxDynamicSharedMemorySize, 51200);
        cudaFuncSetAttribute(hgemm<1,0,4>, cudaFuncAttributeMaxDynamicSharedMemorySize, 51200);
        cudaFuncSetAttribute(hgemm<2,1,1>, cudaFuncAttributeMaxDynamicSharedMemorySize, 51200);
        cudaFuncSetAttribute(hgemm<3,0,1>, cudaFuncAttributeMaxDynamicSharedMemorySize, 51200);
    }

    dim3 blk(256);

    // Fork: weight conversions on side stream, overlapping src conversion / Stage A
    cudaEventRecord(evRoot, 0);
    cudaStreamWaitEvent(sW, evRoot, 0);
    wcvt_fa<<<256, blk, 0, sW>>>(fa_in_w, fa_out_w, Wp);
    cudaEventRecord(evFA, sW);
    wcvt6<<<752, blk, 0, sW>>>(mqw, mdw, muw, mow, l1w, l2w, iqw, ikw, Wp);
    cudaEventRecord(evW, sW);

    // Stage A (main stream)
    cvt_split<<<2048, blk>>>(src, SRCh, SRCl, NTOK*256);
    cudaStreamWaitEvent(0, evFA, 0);
    hgemm<0,0,1><<<dim3(12,64), blk, 51200>>>(SRCh, SRCl, Wp+W_FAIN,
        fa_in_b, nullptr, QKV, nullptr, nullptr, nullptr, NTOK, 768, 256);
    feat_attn<<<2048, blk>>>(QKV, AOh, AOl);
    // fa_out split-K=2: z0 -> X (bias + src residual), z1 -> PART (QKV reuse, safe: after feat_attn)
    hgemm<1,0,2><<<dim3(4,64,2), blk, 51200>>>(AOh, AOl, Wp+W_FAOUT,
        fa_out_b, src, X, nullptr, nullptr, PART, NTOK, 256, 256);
    ln_kernel<<<NTOK/8, blk>>>(X, PART, nullptr, nullptr, n1g, n1b, ST, STh, STl, 1);

    // Merged MQ(fp32) + MD(split) + IDX(fp32) GEMM, N=448
    cudaStreamWaitEvent(0, evW, 0);
    hgemm<3,0,1><<<dim3(7,64), blk, 51200>>>(STh, STl, Wp+W_MQ,
        nullptr, nullptr, MQ, CDh, CDl, IQK, NTOK, 448, 256);

    // Fork indexer branch (scales/quant/topk)
    cudaEventRecord(ev1, 0);
    cudaStreamWaitEvent(sB, ev1, 0);
    idx_scales<<<dim3(8,4,3), blk, 0, sB>>>(IQK, SC);
    idx_quant<<<NTOK*32/256, blk, 0, sB>>>(IQK, SC, QI, KI);
    idx_topk<<<NTOK/8, blk, 0, sB>>>(QI, KI, SC, iow, IDX);
    cudaEventRecord(evB, sB);

    // Stage C (main, concurrent with indexer branch)
    hgemm<0,0,1><<<dim3(8,64), blk, 51200>>>(CDh, CDl, Wp+W_MU,
        nullptr, nullptr, KV, nullptr, nullptr, nullptr, NTOK, 512, 128);

    // Join + attention
    cudaStreamWaitEvent(0, evB, 0);
    mla_attn<<<NTOK, blk>>>(MQ, KV, IDX, AO2h, AO2l);
    // MO split-K=2: z0 -> ST2 (res ST), z1 -> PART
    hgemm<1,0,2><<<dim3(4,64,2), blk, 51200>>>(AO2h, AO2l, Wp+W_MO,
        nullptr, ST, ST2, nullptr, nullptr, PART, NTOK, 256, 256);

    // Stage D
    ln_kernel<<<NTOK/8, blk>>>(ST2, PART, nullptr, nullptr, n2g, n2b, X2, X2h, X2l, 2);
    hgemm<2,1,1><<<dim3(16,64), blk, 51200>>>(X2h, X2l, Wp+W_L1,
        l1b, nullptr, nullptr, H1h, H1l, nullptr, NTOK, 1024, 256);
    // L2 split-K=4: z0 -> X3 (bias + X2 residual), z1..3 -> PART slabs
    hgemm<1,0,4><<<dim3(4,64,4), blk, 51200>>>(H1h, H1l, Wp+W_L2,
        l2b, X2, X3, nullptr, nullptr, PART, NTOK, 256, 1024);
    ln_kernel<<<NTOK/8, blk>>>(X3, PART, PART + (size_t)NTOK*256, PART + (size_t)2*NTOK*256,
        n3g, n3b, (float*)d_out, nullptr, nullptr, 0);
}

// round 14
// speedup vs baseline: 1.0147x; 1.0147x over previous
#include <cuda_runtime.h>
#include <cuda_fp16.h>
#include <math.h>
#include <float.h>
#include <stdint.h>

// ---------------- problem constants ----------------
#define NTOK   8192          // B*R*C tokens = 2*1024*4
#define EDIM   256
#define SPLIT  768
#define TOPK_  32
#define LATD   128
#define MLPD   1024

// ---------------- device scratch (no allocs allowed) ----------------
__device__ float g_QKV[NTOK*768];
__device__ float g_X  [NTOK*EDIM];
__device__ float g_ST [NTOK*EDIM];
__device__ float g_IQK[NTOK*64];
__device__ float g_SC [3*32];
__device__ int   g_QI [NTOK*8];
__device__ int   g_KI [NTOK*8];
__device__ int   g_IDX[NTOK*TOPK_];
__device__ float g_MQ [NTOK*EDIM];
__device__ float g_KV [NTOK*2*EDIM];
__device__ float g_ST2[NTOK*EDIM];
__device__ float g_X2 [NTOK*EDIM];
__device__ float g_X3 [NTOK*EDIM];
// fp16 split buffers (A-side hi/lo; W single fp16)
__device__ __half g_SRCh[NTOK*EDIM],  g_SRCl[NTOK*EDIM];
__device__ __half g_AOh [NTOK*EDIM],  g_AOl [NTOK*EDIM];
__device__ __half g_STh [NTOK*EDIM],  g_STl [NTOK*EDIM];
__device__ __half g_CDh [NTOK*LATD],  g_CDl [NTOK*LATD];
__device__ __half g_AO2h[NTOK*EDIM],  g_AO2l[NTOK*EDIM];
__device__ __half g_X2h [NTOK*EDIM],  g_X2l [NTOK*EDIM];
__device__ __half g_H1h [NTOK*MLPD],  g_H1l [NTOK*MLPD];
__device__ __half g_W   [1<<20];

// weight offsets inside g_W (idx rows packed right after MD for merged N=448 GEMM)
#define W_FAIN  0
#define W_FAOUT 196608
#define W_MQ    262144
#define W_MD    327680
#define W_IDX   360448
#define W_MU    376832
#define W_MO    442368
#define W_L1    507904
#define W_L2    770048

// ---------------- helpers ----------------
__device__ __forceinline__ uint32_t s2u(const void* p) {
    uint32_t a;
    asm("{ .reg .u64 t; cvta.to.shared.u64 t, %1; cvt.u32.u64 %0, t; }" : "=r"(a) : "l"(p));
    return a;
}
__device__ __forceinline__ void ldsm4(uint32_t* r, uint32_t addr) {
    asm volatile("ldmatrix.sync.aligned.m8n8.x4.shared.b16 {%0,%1,%2,%3}, [%4];"
                 : "=r"(r[0]), "=r"(r[1]), "=r"(r[2]), "=r"(r[3]) : "r"(addr));
}
__device__ __forceinline__ void mma16816(float* d, const uint32_t* a, const uint32_t* b) {
    asm volatile("mma.sync.aligned.m16n8k16.row.col.f32.f16.f16.f32 "
                 "{%0,%1,%2,%3}, {%4,%5,%6,%7}, {%8,%9}, {%0,%1,%2,%3};"
                 : "+f"(d[0]), "+f"(d[1]), "+f"(d[2]), "+f"(d[3])
                 : "r"(a[0]), "r"(a[1]), "r"(a[2]), "r"(a[3]), "r"(b[0]), "r"(b[1]));
}
#define CPA(dst, src) asm volatile("cp.async.cg.shared.global [%0], [%1], 16;" :: "r"(dst), "l"(src))
#define CPA_COMMIT()  asm volatile("cp.async.commit_group;" ::: "memory")
#define CPA_WAIT1()   asm volatile("cp.async.wait_group 1;" ::: "memory")
#define CPA_WAIT0()   asm volatile("cp.async.wait_group 0;" ::: "memory")

__device__ __forceinline__ __half2 split_hi(float a, float b, __half2& lo) {
    __half2 hi;
    hi.x = __float2half_rn(a); hi.y = __float2half_rn(b);
    lo.x = __float2half_rn(a - __half2float(hi.x));
    lo.y = __float2half_rn(b - __half2float(hi.y));
    return hi;
}
__device__ __forceinline__ void cvt4(const float* __restrict__ x, __half* __restrict__ hi,
                                     __half* __restrict__ lo, int i) {
    float4 v = *reinterpret_cast<const float4*>(x + i);
    __half2 l0, l1;
    __half2 h0 = split_hi(v.x, v.y, l0);
    __half2 h1 = split_hi(v.z, v.w, l1);
    *reinterpret_cast<__half2*>(hi + i)     = h0;
    *reinterpret_cast<__half2*>(hi + i + 2) = h1;
    *reinterpret_cast<__half2*>(lo + i)     = l0;
    *reinterpret_cast<__half2*>(lo + i + 2) = l1;
}
__device__ __forceinline__ void cvt4w(const float* __restrict__ x, __half* __restrict__ w, int i) {
    float4 v = *reinterpret_cast<const float4*>(x + i);
    __half2 h0; h0.x = __float2half_rn(v.x); h0.y = __float2half_rn(v.y);
    __half2 h1; h1.x = __float2half_rn(v.z); h1.y = __float2half_rn(v.w);
    *reinterpret_cast<__half2*>(w + i)     = h0;
    *reinterpret_cast<__half2*>(w + i + 2) = h1;
}

// ---------------- conversions ----------------
__global__ void cvt_split(const float* __restrict__ x, __half* __restrict__ hi,
                          __half* __restrict__ lo, int n) {
    int i = (blockIdx.x * 256 + threadIdx.x) * 4;
    if (i < n) cvt4(x, hi, lo, i);
}

__global__ void wcvt_fa(const float* __restrict__ fin, const float* __restrict__ fout,
                        __half* __restrict__ W) {
    int b = blockIdx.x;
    const float* src; int dst, rel;
    if (b < 192) { src = fin;  dst = W_FAIN;  rel = b; }
    else         { src = fout; dst = W_FAOUT; rel = b - 192; }
    int i = (rel*256 + threadIdx.x)*4;
    cvt4w(src, W + dst, i);
}

__global__ void wcvt6(const float* __restrict__ mq, const float* __restrict__ md,
                      const float* __restrict__ mu, const float* __restrict__ mo,
                      const float* __restrict__ l1, const float* __restrict__ l2,
                      const float* __restrict__ iq, const float* __restrict__ ik,
                      __half* __restrict__ W) {
    int b = blockIdx.x;
    const float* src; int dst, rel;
    if (b < 64)       { src = mq; dst = W_MQ;        rel = b; }
    else if (b < 96)  { src = md; dst = W_MD;        rel = b-64; }
    else if (b < 104) { src = iq; dst = W_IDX;       rel = b-96; }
    else if (b < 112) { src = ik; dst = W_IDX+8192;  rel = b-104; }
    else if (b < 176) { src = mu; dst = W_MU;        rel = b-112; }
    else if (b < 240) { src = mo; dst = W_MO;        rel = b-176; }
    else if (b < 496) { src = l1; dst = W_L1;        rel = b-240; }
    else              { src = l2; dst = W_L2;        rel = b-496; }
    int i = (rel*256 + threadIdx.x)*4;
    cvt4w(src, W + dst, i);
}

// ---------------- HMMA fp16 2-term GEMM, BM=128, BN=64, 3-stage pipeline, 3 CTA/SM ----
// D = Ah*W + Al*W.
// EPI: 0 +bias(opt); 1 +bias(opt)+res; 2 gelu(acc+bias) split-out; 3 MQ/CD/IQK mixed
#define PADH 40   // halves per smem row (80B stride)
#define STAGE 25600   // 20480 (A hi+lo) + 5120 (B)
#define NSTG  3

template<int EPI, int OSPLIT>
__global__ void __launch_bounds__(256, 3)
hgemm(const __half* __restrict__ Ahi, const __half* __restrict__ Alo,
      const __half* __restrict__ W,
      const float* __restrict__ bias, const float* __restrict__ res,
      float* __restrict__ C, __half* __restrict__ Chi, __half* __restrict__ Clo,
      float* __restrict__ C2,
      int M, int N, int K) {
    constexpr int WNT  = 32;
    constexpr int NPI  = 2;
    constexpr int NNI  = 4;

    extern __shared__ __align__(16) char smem[];
    const uint32_t sb = s2u(smem);
    const int tid  = threadIdx.x;
    const int warp = tid >> 5, lane = tid & 31;
    const int wm = warp & 3, wn = warp >> 2;
    const int bm = blockIdx.y * 128, bn = blockIdx.x * 64;

    float acc[2][NNI][4];
    #pragma unroll
    for (int i = 0; i < 2; i++)
        #pragma unroll
        for (int j = 0; j < NNI; j++)
            #pragma unroll
            for (int l = 0; l < 4; l++) acc[i][j][l] = 0.0f;

    const int a_r = (lane & 7) + ((lane >> 3) & 1) * 8;
    const int a_c = ((lane >> 4) & 1) * 8;
    const int b_r = (lane & 7) + ((lane >> 4) & 1) * 8;
    const int b_c = ((lane >> 3) & 1) * 8;

    const int nch = K >> 5;

    auto load_stage = [&](int st, int k0) {
        uint32_t base = sb + st*STAGE;
        #pragma unroll
        for (int c = tid; c < 512; c += 256) {
            int row = c >> 2, seg = c & 3;
            uint32_t d = base + row*80 + seg*16;
            CPA(d,         Ahi + (size_t)(bm + row)*K + k0 + seg*8);
            CPA(d + 10240, Alo + (size_t)(bm + row)*K + k0 + seg*8);
        }
        {
            int row = tid >> 2, seg = tid & 3;
            uint32_t d = base + 20480 + row*80 + seg*16;
            CPA(d, W + (size_t)(bn + row)*K + k0 + seg*8);
        }
        CPA_COMMIT();
    };

    // prologue: stages 0 and 1
    load_stage(0, 0);
    if (nch > 1) load_stage(1, 32);

    int st = 0;
    for (int c = 0; c < nch; c++) {
        CPA_WAIT1();
        __syncthreads();
        // prefetch stage c+2 (overwrites stage computed at iter c-1; barrier above protects it)
        if (c + 2 < nch) {
            int st2 = st + 2; if (st2 >= NSTG) st2 -= NSTG;
            load_stage(st2, (c + 2) << 5);
        }

        const uint32_t base = sb + st*STAGE;
        #pragma unroll
        for (int ks = 0; ks < 2; ks++) {
            uint32_t ah[2][4], al[2][4];
            #pragma unroll
            for (int mi = 0; mi < 2; mi++) {
                uint32_t off = base + ((wm*32 + mi*16 + a_r)*PADH + ks*16 + a_c) * 2;
                ldsm4(ah[mi], off);
                ldsm4(al[mi], off + 10240);
            }
            uint32_t bh[NNI][2];
            #pragma unroll
            for (int pi = 0; pi < NPI; pi++) {
                uint32_t off = base + 20480 + ((wn*WNT + pi*16 + b_r)*PADH + ks*16 + b_c) * 2;
                uint32_t t[4];
                ldsm4(t, off);
                bh[2*pi][0]=t[0]; bh[2*pi][1]=t[1]; bh[2*pi+1][0]=t[2]; bh[2*pi+1][1]=t[3];
            }
            #pragma unroll
            for (int ni = 0; ni < NNI; ni++)
                #pragma unroll
                for (int mi = 0; mi < 2; mi++) {
                    mma16816(acc[mi][ni], ah[mi], bh[ni]);
                    mma16816(acc[mi][ni], al[mi], bh[ni]);
                }
        }
        st++; if (st >= NSTG) st = 0;
    }

    const int gr = lane >> 2, gc = (lane & 3) * 2;
    #pragma unroll
    for (int mi = 0; mi < 2; mi++) {
        #pragma unroll
        for (int ni = 0; ni < NNI; ni++) {
            int r0 = bm + wm*32 + mi*16 + gr;
            int cc = bn + wn*WNT + ni*8 + gc;
            float2 v0 = make_float2(acc[mi][ni][0], acc[mi][ni][1]);
            float2 v1 = make_float2(acc[mi][ni][2], acc[mi][ni][3]);
            if (EPI != 3 && bias) {
                float2 bz = *reinterpret_cast<const float2*>(bias + cc);
                v0.x += bz.x; v0.y += bz.y; v1.x += bz.x; v1.y += bz.y;
            }
            if (EPI == 1) {
                float2 r0v = *reinterpret_cast<const float2*>(res + (size_t)r0*N + cc);
                float2 r1v = *reinterpret_cast<const float2*>(res + (size_t)(r0+8)*N + cc);
                v0.x += r0v.x; v0.y += r0v.y; v1.x += r1v.x; v1.y += r1v.y;
            }
            if (EPI == 2) {
                v0.x = 0.5f*v0.x*(1.0f + erff(v0.x*0.7071067811865475f));
                v0.y = 0.5f*v0.y*(1.0f + erff(v0.y*0.7071067811865475f));
                v1.x = 0.5f*v1.x*(1.0f + erff(v1.x*0.7071067811865475f));
                v1.y = 0.5f*v1.y*(1.0f + erff(v1.y*0.7071067811865475f));
            }
            if (EPI == 3) {
                if (cc < 256) {
                    *reinterpret_cast<float2*>(C + (size_t)r0*256 + cc)     = v0;
                    *reinterpret_cast<float2*>(C + (size_t)(r0+8)*256 + cc) = v1;
                } else if (cc < 384) {
                    int c2 = cc - 256;
                    __half2 l0, l1;
                    __half2 h0 = split_hi(v0.x, v0.y, l0);
                    __half2 h1 = split_hi(v1.x, v1.y, l1);
                    *reinterpret_cast<__half2*>(Chi + (size_t)r0*128 + c2)     = h0;
                    *reinterpret_cast<__half2*>(Clo + (size_t)r0*128 + c2)     = l0;
                    *reinterpret_cast<__half2*>(Chi + (size_t)(r0+8)*128 + c2) = h1;
                    *reinterpret_cast<__half2*>(Clo + (size_t)(r0+8)*128 + c2) = l1;
                } else {
                    int c2 = cc - 384;
                    *reinterpret_cast<float2*>(C2 + (size_t)r0*64 + c2)     = v0;
                    *reinterpret_cast<float2*>(C2 + (size_t)(r0+8)*64 + c2) = v1;
                }
            } else if (OSPLIT) {
                __half2 l0, l1;
                __half2 h0 = split_hi(v0.x, v0.y, l0);
                __half2 h1 = split_hi(v1.x, v1.y, l1);
                *reinterpret_cast<__half2*>(Chi + (size_t)r0*N + cc)     = h0;
                *reinterpret_cast<__half2*>(Clo + (size_t)r0*N + cc)     = l0;
                *reinterpret_cast<__half2*>(Chi + (size_t)(r0+8)*N + cc) = h1;
                *reinterpret_cast<__half2*>(Clo + (size_t)(r0+8)*N + cc) = l1;
            } else {
                *reinterpret_cast<float2*>(C + (size_t)r0*N + cc)     = v0;
                *reinterpret_cast<float2*>(C + (size_t)(r0+8)*N + cc) = v1;
            }
        }
    }
}

// ---------------- feature attention over C=4 tokens (fp16 split output) ----------------
__global__ void feat_attn(const float* __restrict__ QKV,
                          __half* __restrict__ AOh, __half* __restrict__ AOl) {
    int s = blockIdx.x;
    int h = threadIdx.x >> 5;
    int lane = threadIdx.x & 31;
    float q[4], k[4], v[4];
    #pragma unroll
    for (int c = 0; c < 4; c++) {
        const float* row = QKV + (size_t)(s*4 + c) * 768;
        q[c] = row[h*32 + lane];
        k[c] = row[256 + h*32 + lane];
        v[c] = row[512 + h*32 + lane];
    }
    float sc[4][4];
    #pragma unroll
    for (int a = 0; a < 4; a++)
        #pragma unroll
        for (int b = 0; b < 4; b++) {
            float p = q[a] * k[b];
            #pragma unroll
            for (int o = 16; o > 0; o >>= 1) p += __shfl_xor_sync(0xffffffffu, p, o);
            sc[a][b] = p * 0.17677669529663687f;
        }
    #pragma unroll
    for (int a = 0; a < 4; a++) {
        float mx = fmaxf(fmaxf(sc[a][0], sc[a][1]), fmaxf(sc[a][2], sc[a][3]));
        float e0 = expf(sc[a][0]-mx), e1 = expf(sc[a][1]-mx);
        float e2 = expf(sc[a][2]-mx), e3 = expf(sc[a][3]-mx);
        float den = e0 + e1 + e2 + e3;
        float o = (e0*v[0] + e1*v[1] + e2*v[2] + e3*v[3]) / den;
        __half oh = __float2half_rn(o);
        __half ol = __float2half_rn(o - __half2float(oh));
        size_t idx = (size_t)(s*4 + a)*256 + h*32 + lane;
        AOh[idx] = oh;
        AOl[idx] = ol;
    }
}

// ---------------- layernorm, warp-per-token, layout remap, optional split out ----------------
__global__ void ln_kernel(const float* __restrict__ X, const float* __restrict__ g,
                          const float* __restrict__ b, float* __restrict__ Y,
                          __half* __restrict__ Yhi, __half* __restrict__ Ylo, int mode) {
    int t = blockIdx.x * 8 + (threadIdx.x >> 5);
    int lane = threadIdx.x & 31;
    const float* xr = X + (size_t)t * 256 + lane * 8;
    float4 x0 = *reinterpret_cast<const float4*>(xr);
    float4 x1 = *reinterpret_cast<const float4*>(xr + 4);
    float s = x0.x + x0.y + x0.z + x0.w + x1.x + x1.y + x1.z + x1.w;
    #pragma unroll
    for (int o = 16; o > 0; o >>= 1) s += __shfl_xor_sync(0xffffffffu, s, o);
    float m = s * (1.0f / 256.0f);
    float d[8] = {x0.x-m, x0.y-m, x0.z-m, x0.w-m, x1.x-m, x1.y-m, x1.z-m, x1.w-m};
    float vs = 0.f;
    #pragma unroll
    for (int i = 0; i < 8; i++) vs += d[i]*d[i];
    #pragma unroll
    for (int o = 16; o > 0; o >>= 1) vs += __shfl_xor_sync(0xffffffffu, vs, o);
    float inv = rsqrtf(vs * (1.0f/256.0f) + 1e-5f);
    float y[8];
    const float* gp = g + lane*8;
    const float* bp = b + lane*8;
    #pragma unroll
    for (int i = 0; i < 8; i++) y[i] = d[i]*inv*gp[i] + bp[i];
    int ot;
    if (mode == 0) ot = t;
    else if (mode == 1) { int bb = t >> 12, r = (t >> 2) & 1023, c = t & 3; ot = ((bb<<2)|c)*1024 + r; }
    else { int bf = t >> 10, r = t & 1023; int bb = bf >> 2, c = bf & 3; ot = bb*4096 + r*4 + c; }
    float* yr = Y + (size_t)ot * 256 + lane * 8;
    *reinterpret_cast<float4*>(yr)     = make_float4(y[0], y[1], y[2], y[3]);
    *reinterpret_cast<float4*>(yr + 4) = make_float4(y[4], y[5], y[6], y[7]);
    if (Yhi) {
        size_t o2 = (size_t)ot * 256 + lane * 8;
        #pragma unroll
        for (int i = 0; i < 4; i++) {
            __half2 lo;
            __half2 hi = split_hi(y[2*i], y[2*i+1], lo);
            *reinterpret_cast<__half2*>(Yhi + o2 + 2*i) = hi;
            *reinterpret_cast<__half2*>(Ylo + o2 + 2*i) = lo;
        }
    }
}

// ---------------- indexer: scales / quantize / score+topk ----------------
__global__ void idx_scales(const float* __restrict__ IQK, float* __restrict__ SC) {
    int bf = blockIdx.x, h = blockIdx.y, kind = blockIdx.z;
    int r0 = (kind == 1) ? SPLIT : 0;
    int r1 = (kind == 1) ? 1024 : SPLIT;
    int cb = (kind == 2) ? 32 : 0;
    int n = (r1 - r0) * 8;
    float m = 0.0f;
    for (int i = threadIdx.x; i < n; i += 256) {
        int r = r0 + (i >> 3), d = i & 7;
        m = fmaxf(m, fabsf(IQK[(size_t)(bf*1024 + r)*64 + cb + h*8 + d]));
    }
    __shared__ float sm[8];
    #pragma unroll
    for (int o = 16; o > 0; o >>= 1) m = fmaxf(m, __shfl_xor_sync(0xffffffffu, m, o));
    if ((threadIdx.x & 31) == 0) sm[threadIdx.x >> 5] = m;
    __syncthreads();
    if (threadIdx.x == 0) {
        float mm = sm[0];
        for (int i = 1; i < 8; i++) mm = fmaxf(mm, sm[i]);
        SC[kind*32 + bf*4 + h] = (mm + 1e-6f) / 127.0f;
    }
}

__global__ void idx_quant(const float* __restrict__ IQK, const float* __restrict__ SC,
                          int* __restrict__ QI, int* __restrict__ KI) {
    int idx = blockIdx.x * 256 + threadIdx.x;
    if (idx >= NTOK*32) return;
    int t = idx >> 5, j = idx & 31, h = j >> 3;
    int bf = t >> 10, r = t & 1023;
    char* qb = (char*)QI;
    char* kb = (char*)KI;
    float qs = SC[(r < SPLIT ? 0 : 1)*32 + bf*4 + h];
    float qv = rintf(IQK[(size_t)t*64 + j] / qs);
    qv = fminf(fmaxf(qv, -127.0f), 127.0f);
    qb[idx] = (char)(int)qv;
    if (r < SPLIT) {
        float ks = SC[64 + bf*4 + h];
        float kv = rintf(IQK[(size_t)t*64 + 32 + j] / ks);
        kv = fminf(fmaxf(kv, -127.0f), 127.0f);
        kb[idx] = (char)(int)kv;
    } else {
        kb[idx] = 0;
    }
}

// warp-per-token top-k: scores in 24 regs/lane, 32 argmax rounds, no block barriers
__global__ void idx_topk(const int* __restrict__ QI, const int* __restrict__ KI,
                         const float* __restrict__ SC, const float* __restrict__ ow,
                         int* __restrict__ IDX) {
    int warp = threadIdx.x >> 5, lane = threadIdx.x & 31;
    int t = blockIdx.x * 8 + warp;
    int bf = t >> 10, r = t & 1023;

    int4 q0 = *reinterpret_cast<const int4*>(QI + (size_t)t*8);
    int4 q1 = *reinterpret_cast<const int4*>(QI + (size_t)t*8 + 4);
    int qw[8] = {q0.x, q0.y, q0.z, q0.w, q1.x, q1.y, q1.z, q1.w};

    float ssc[4], sow[4];
    #pragma unroll
    for (int h = 0; h < 4; h++) {
        float qs = SC[(r < SPLIT ? 0 : 1)*32 + bf*4 + h];
        ssc[h] = qs * SC[64 + bf*4 + h];
        sow[h] = ow[h];
    }

    float rv[24];
    #pragma unroll
    for (int i = 0; i < 24; i++) {
        int k = i*32 + lane;
        const int* kw = KI + (size_t)(bf*1024 + k)*8;
        int4 k0 = *reinterpret_cast<const int4*>(kw);
        int4 k1 = *reinterpret_cast<const int4*>(kw + 4);
        int kwv[8] = {k0.x, k0.y, k0.z, k0.w, k1.x, k1.y, k1.z, k1.w};
        float acc = 0.f;
        #pragma unroll
        for (int h = 0; h < 4; h++) {
            int d = __dp4a(qw[2*h], kwv[2*h], __dp4a(qw[2*h+1], kwv[2*h+1], 0));
            acc += fmaxf((float)d * ssc[h], 0.0f) * sow[h];
        }
        rv[i] = acc;
    }

    for (int sel = 0; sel < TOPK_; sel++) {
        float bv = -FLT_MAX; int bi = 0x7fffffff;
        #pragma unroll
        for (int i = 0; i < 24; i++) {
            if (rv[i] > bv) { bv = rv[i]; bi = i*32 + lane; }
        }
        #pragma unroll
        for (int o = 16; o > 0; o >>= 1) {
            float ov = __shfl_xor_sync(0xffffffffu, bv, o);
            int   oi = __shfl_xor_sync(0xffffffffu, bi, o);
            if (ov > bv || (ov == bv && oi < bi)) { bv = ov; bi = oi; }
        }
        if (lane == 0) IDX[t*TOPK_ + sel] = bi;
        if ((bi & 31) == lane) rv[bi >> 5] = -FLT_MAX;
    }
}

// ---------------- sparse MLA attention v2: smem-staged, shuffle-light ----------------
__global__ void mla_attn(const float* __restrict__ MQ, const float* __restrict__ KV,
                         const int* __restrict__ IDX,
                         __half* __restrict__ AO2h, __half* __restrict__ AO2l) {
    __shared__ float sBuf[8][32][33];
    __shared__ float sQ[8][32];
    __shared__ float sW[8][32];
    __shared__ int sidx[32];

    int t = blockIdx.x;
    int bf = t >> 10;
    int h = threadIdx.x >> 5, lane = threadIdx.x & 31;

    if (threadIdx.x < 32) sidx[threadIdx.x] = IDX[t*TOPK_ + threadIdx.x];
    float q = MQ[(size_t)t*256 + h*32 + lane];
    sQ[h][lane] = q;
    __syncthreads();

    #pragma unroll 4
    for (int j = 0; j < 32; j++) {
        int kt = bf*1024 + sidx[j];
        sBuf[h][j][lane] = KV[(size_t)kt*512 + h*32 + lane];
    }
    __syncwarp();

    float score = 0.0f;
    #pragma unroll
    for (int d = 0; d < 32; d++)
        score += sQ[h][d] * sBuf[h][lane][d];
    score *= 0.17677669529663687f;

    float mx = score;
    #pragma unroll
    for (int o = 16; o > 0; o >>= 1) mx = fmaxf(mx, __shfl_xor_sync(0xffffffffu, mx, o));
    float e = expf(score - mx);
    float ssum = e;
    #pragma unroll
    for (int o = 16; o > 0; o >>= 1) ssum += __shfl_xor_sync(0xffffffffu, ssum, o);
    sW[h][lane] = e / ssum;
    __syncwarp();

    #pragma unroll 4
    for (int j = 0; j < 32; j++) {
        int kt = bf*1024 + sidx[j];
        sBuf[h][j][lane] = KV[(size_t)kt*512 + 256 + h*32 + lane];
    }
    __syncwarp();

    float acc = 0.0f;
    #pragma unroll
    for (int j = 0; j < 32; j++)
        acc += sW[h][j] * sBuf[h][j][lane];

    __half oh = __float2half_rn(acc);
    __half ol = __float2half_rn(acc - __half2float(oh));
    size_t idx = (size_t)t*256 + h*32 + lane;
    AO2h[idx] = oh;
    AO2l[idx] = ol;
}

// ---------------- host launcher ----------------
static float* symF(const void* sym) { void* p = nullptr; cudaGetSymbolAddress(&p, sym); return (float*)p; }
static int*   symI(const void* sym) { void* p = nullptr; cudaGetSymbolAddress(&p, sym); return (int*)p; }
static __half* symH(const void* sym) { void* p = nullptr; cudaGetSymbolAddress(&p, sym); return (__half*)p; }

extern "C" void kernel_launch(void* const* d_in, const int* in_sizes, int n_in,
                              void* d_out, int out_size) {
    (void)in_sizes; (void)n_in; (void)out_size;
    const float* src      = (const float*)d_in[0];
    const float* fa_in_w  = (const float*)d_in[2];
    const float* fa_in_b  = (const float*)d_in[3];
    const float* fa_out_w = (const float*)d_in[4];
    const float* fa_out_b = (const float*)d_in[5];
    const float* n1g = (const float*)d_in[6];
    const float* n1b = (const float*)d_in[7];
    const float* iqw = (const float*)d_in[8];
    const float* ikw = (const float*)d_in[9];
    const float* iow = (const float*)d_in[10];
    const float* mqw = (const float*)d_in[11];
    const float* mdw = (const float*)d_in[12];
    const float* muw = (const float*)d_in[13];
    const float* mow = (const float*)d_in[14];
    const float* n2g = (const float*)d_in[15];
    const float* n2b = (const float*)d_in[16];
    const float* l1w = (const float*)d_in[17];
    const float* l1b = (const float*)d_in[18];
    const float* l2w = (const float*)d_in[19];
    const float* l2b = (const float*)d_in[20];
    const float* n3g = (const float*)d_in[21];
    const float* n3b = (const float*)d_in[22];

    float* QKV = symF(g_QKV); float* X   = symF(g_X);   float* ST  = symF(g_ST);
    float* IQK = symF(g_IQK); float* SC  = symF(g_SC);
    int*   QI  = symI(g_QI);  int*   KI  = symI(g_KI);  int*   IDX = symI(g_IDX);
    float* MQ  = symF(g_MQ);  float* KV  = symF(g_KV);  float* ST2 = symF(g_ST2);
    float* X2  = symF(g_X2);  float* X3  = symF(g_X3);
    __half *SRCh=symH(g_SRCh), *SRCl=symH(g_SRCl);
    __half *AOh=symH(g_AOh),   *AOl=symH(g_AOl);
    __half *STh=symH(g_STh),   *STl=symH(g_STl);
    __half *CDh=symH(g_CDh),   *CDl=symH(g_CDl);
    __half *AO2h=symH(g_AO2h), *AO2l=symH(g_AO2l);
    __half *X2h=symH(g_X2h),   *X2l=symH(g_X2l);
    __half *H1h=symH(g_H1h),   *H1l=symH(g_H1l);
    __half *Wp=symH(g_W);

    static cudaStream_t sW = nullptr, sB = nullptr;
    static cudaEvent_t evRoot = nullptr, evFA = nullptr, evW = nullptr, ev1 = nullptr, evB = nullptr;
    if (!sW) {
        cudaStreamCreateWithFlags(&sW, cudaStreamNonBlocking);
        cudaStreamCreateWithFlags(&sB, cudaStreamNonBlocking);
        cudaEventCreateWithFlags(&evRoot, cudaEventDisableTiming);
        cudaEventCreateWithFlags(&evFA,  cudaEventDisableTiming);
        cudaEventCreateWithFlags(&evW,   cudaEventDisableTiming);
        cudaEventCreateWithFlags(&ev1,   cudaEventDisableTiming);
        cudaEventCreateWithFlags(&evB,   cudaEventDisableTiming);
        cudaFuncSetAttribute(hgemm<0,0>, cudaFuncAttributeMaxDynamicSharedMemorySize, 76800);
        cudaFuncSetAttribute(hgemm<1,0>, cudaFuncAttributeMaxDynamicSharedMemorySize, 76800);
        cudaFuncSetAttribute(hgemm<2,1>, cudaFuncAttributeMaxDynamicSharedMemorySize, 76800);
        cudaFuncSetAttribute(hgemm<3,0>, cudaFuncAttributeMaxDynamicSharedMemorySize, 76800);
    }

    dim3 blk(256);

    // Fork: weight conversions on side stream, overlapping src conversion / Stage A
    cudaEventRecord(evRoot, 0);
    cudaStreamWaitEvent(sW, evRoot, 0);
    wcvt_fa<<<256, blk, 0, sW>>>(fa_in_w, fa_out_w, Wp);
    cudaEventRecord(evFA, sW);
    wcvt6<<<752, blk, 0, sW>>>(mqw, mdw, muw, mow, l1w, l2w, iqw, ikw, Wp);
    cudaEventRecord(evW, sW);

    // Stage A (main stream)
    cvt_split<<<2048, blk>>>(src, SRCh, SRCl, NTOK*256);
    cudaStreamWaitEvent(0, evFA, 0);
    hgemm<0,0><<<dim3(12,64), blk, 76800>>>(SRCh, SRCl, Wp+W_FAIN,
        fa_in_b, nullptr, QKV, nullptr, nullptr, nullptr, NTOK, 768, 256);
    feat_attn<<<2048, blk>>>(QKV, AOh, AOl);
    hgemm<1,0><<<dim3(4,64), blk, 76800>>>(AOh, AOl, Wp+W_FAOUT,
        fa_out_b, src, X, nullptr, nullptr, nullptr, NTOK, 256, 256);
    ln_kernel<<<NTOK/8, blk>>>(X, n1g, n1b, ST, STh, STl, 1);

    // Merged MQ(fp32) + MD(split) + IDX(fp32) GEMM, N=448
    cudaStreamWaitEvent(0, evW, 0);
    hgemm<3,0><<<dim3(7,64), blk, 76800>>>(STh, STl, Wp+W_MQ,
        nullptr, nullptr, MQ, CDh, CDl, IQK, NTOK, 448, 256);

    // Fork indexer branch (scales/quant/topk)
    cudaEventRecord(ev1, 0);
    cudaStreamWaitEvent(sB, ev1, 0);
    idx_scales<<<dim3(8,4,3), blk, 0, sB>>>(IQK, SC);
    idx_quant<<<NTOK*32/256, blk, 0, sB>>>(IQK, SC, QI, KI);
    idx_topk<<<NTOK/8, blk, 0, sB>>>(QI, KI, SC, iow, IDX);
    cudaEventRecord(evB, sB);

    // Stage C (main, concurrent with indexer branch)
    hgemm<0,0><<<dim3(8,64), blk, 76800>>>(CDh, CDl, Wp+W_MU,
        nullptr, nullptr, KV, nullptr, nullptr, nullptr, NTOK, 512, 128);

    // Join + attention
    cudaStreamWaitEvent(0, evB, 0);
    mla_attn<<<NTOK, blk>>>(MQ, KV, IDX, AO2h, AO2l);
    hgemm<1,0><<<dim3(4,64), blk, 76800>>>(AO2h, AO2l, Wp+W_MO,
        nullptr, ST, ST2, nullptr, nullptr, nullptr, NTOK, 256, 256);

    // Stage D
    ln_kernel<<<NTOK/8, blk>>>(ST2, n2g, n2b, X2, X2h, X2l, 2);
    hgemm<2,1><<<dim3(16,64), blk, 76800>>>(X2h, X2l, Wp+W_L1,
        l1b, nullptr, nullptr, H1h, H1l, nullptr, NTOK, 1024, 256);
    hgemm<1,0><<<dim3(4,64), blk, 76800>>>(H1h, H1l, Wp+W_L2,
        l2b, X2, X3, nullptr, nullptr, nullptr, NTOK, 256, 1024);
    ln_kernel<<<NTOK/8, blk>>>(X3, n3g, n3b, (float*)d_out, nullptr, nullptr, 0);
}

// round 15
// speedup vs baseline: 1.1885x; 1.1713x over previous
#include <cuda_runtime.h>
#include <cuda_fp16.h>
#include <math.h>
#include <float.h>
#include <stdint.h>

// ---------------- problem constants ----------------
#define NTOK   8192          // B*R*C tokens = 2*1024*4
#define EDIM   256
#define SPLIT  768
#define TOPK_  32
#define LATD   128
#define MLPD   1024

// ---------------- device scratch (no allocs allowed) ----------------
__device__ float g_QKV[NTOK*768];
__device__ float g_X  [NTOK*EDIM];
__device__ float g_ST [NTOK*EDIM];
__device__ float g_IQK[NTOK*64];
__device__ float g_SC [3*32];
__device__ int   g_QI [NTOK*8];
__device__ int   g_KI [NTOK*8];
__device__ int   g_IDX[NTOK*TOPK_];
__device__ float g_MQ [NTOK*EDIM];
__device__ float g_KV [NTOK*2*EDIM];
__device__ float g_ST2[NTOK*EDIM];
__device__ float g_X2 [NTOK*EDIM];
__device__ float g_X3 [NTOK*EDIM];
// fp16 activation buffers (single term) + weights
__device__ __half g_SRCh[NTOK*EDIM];
__device__ __half g_AOh [NTOK*EDIM];
__device__ __half g_STh [NTOK*EDIM];
__device__ __half g_CDh [NTOK*LATD];
__device__ __half g_AO2h[NTOK*EDIM];
__device__ __half g_X2h [NTOK*EDIM];
__device__ __half g_H1h [NTOK*MLPD];
__device__ __half g_W   [1<<20];

// weight offsets inside g_W (idx rows packed right after MD for merged N=448 GEMM)
#define W_FAIN  0
#define W_FAOUT 196608
#define W_MQ    262144
#define W_MD    327680
#define W_IDX   360448
#define W_MU    376832
#define W_MO    442368
#define W_L1    507904
#define W_L2    770048

// ---------------- helpers ----------------
__device__ __forceinline__ uint32_t s2u(const void* p) {
    uint32_t a;
    asm("{ .reg .u64 t; cvta.to.shared.u64 t, %1; cvt.u32.u64 %0, t; }" : "=r"(a) : "l"(p));
    return a;
}
__device__ __forceinline__ void ldsm4(uint32_t* r, uint32_t addr) {
    asm volatile("ldmatrix.sync.aligned.m8n8.x4.shared.b16 {%0,%1,%2,%3}, [%4];"
                 : "=r"(r[0]), "=r"(r[1]), "=r"(r[2]), "=r"(r[3]) : "r"(addr));
}
__device__ __forceinline__ void mma16816(float* d, const uint32_t* a, const uint32_t* b) {
    asm volatile("mma.sync.aligned.m16n8k16.row.col.f32.f16.f16.f32 "
                 "{%0,%1,%2,%3}, {%4,%5,%6,%7}, {%8,%9}, {%0,%1,%2,%3};"
                 : "+f"(d[0]), "+f"(d[1]), "+f"(d[2]), "+f"(d[3])
                 : "r"(a[0]), "r"(a[1]), "r"(a[2]), "r"(a[3]), "r"(b[0]), "r"(b[1]));
}
#define CPA(dst, src) asm volatile("cp.async.cg.shared.global [%0], [%1], 16;" :: "r"(dst), "l"(src))
#define CPA_COMMIT()  asm volatile("cp.async.commit_group;" ::: "memory")
#define CPA_WAIT1()   asm volatile("cp.async.wait_group 1;" ::: "memory")
#define CPA_WAIT0()   asm volatile("cp.async.wait_group 0;" ::: "memory")

__device__ __forceinline__ void cvt4h(const float* __restrict__ x, __half* __restrict__ h, int i) {
    float4 v = *reinterpret_cast<const float4*>(x + i);
    __half2 h0; h0.x = __float2half_rn(v.x); h0.y = __float2half_rn(v.y);
    __half2 h1; h1.x = __float2half_rn(v.z); h1.y = __float2half_rn(v.w);
    *reinterpret_cast<__half2*>(h + i)     = h0;
    *reinterpret_cast<__half2*>(h + i + 2) = h1;
}

// ---------------- conversions ----------------
__global__ void cvt_h(const float* __restrict__ x, __half* __restrict__ h, int n) {
    int i = (blockIdx.x * 256 + threadIdx.x) * 4;
    if (i < n) cvt4h(x, h, i);
}

__global__ void wcvt_fa(const float* __restrict__ fin, const float* __restrict__ fout,
                        __half* __restrict__ W) {
    int b = blockIdx.x;
    const float* src; int dst, rel;
    if (b < 192) { src = fin;  dst = W_FAIN;  rel = b; }
    else         { src = fout; dst = W_FAOUT; rel = b - 192; }
    int i = (rel*256 + threadIdx.x)*4;
    cvt4h(src, W + dst, i);
}

__global__ void wcvt6(const float* __restrict__ mq, const float* __restrict__ md,
                      const float* __restrict__ mu, const float* __restrict__ mo,
                      const float* __restrict__ l1, const float* __restrict__ l2,
                      const float* __restrict__ iq, const float* __restrict__ ik,
                      __half* __restrict__ W) {
    int b = blockIdx.x;
    const float* src; int dst, rel;
    if (b < 64)       { src = mq; dst = W_MQ;        rel = b; }
    else if (b < 96)  { src = md; dst = W_MD;        rel = b-64; }
    else if (b < 104) { src = iq; dst = W_IDX;       rel = b-96; }
    else if (b < 112) { src = ik; dst = W_IDX+8192;  rel = b-104; }
    else if (b < 176) { src = mu; dst = W_MU;        rel = b-112; }
    else if (b < 240) { src = mo; dst = W_MO;        rel = b-176; }
    else if (b < 496) { src = l1; dst = W_L1;        rel = b-240; }
    else              { src = l2; dst = W_L2;        rel = b-496; }
    int i = (rel*256 + threadIdx.x)*4;
    cvt4h(src, W + dst, i);
}

// ---------------- HMMA fp16 single-term GEMM, BM=128, BN=64, 3-stage, 3 CTA/SM ----
// D = A*W (both fp16, fp32 accum).
// EPI: 0 +bias(opt); 1 +bias(opt)+res; 2 gelu(acc+bias) fp16-out; 3 MQ/CD/IQK mixed
#define PADH 40   // halves per smem row (80B stride)
#define STAGE 15360   // 10240 (A) + 5120 (B)
#define NSTG  3

template<int EPI, int OHALF>
__global__ void __launch_bounds__(256, 3)
hgemm(const __half* __restrict__ A, const __half* __restrict__ W,
      const float* __restrict__ bias, const float* __restrict__ res,
      float* __restrict__ C, __half* __restrict__ Ch, float* __restrict__ C2,
      int M, int N, int K) {
    constexpr int WNT  = 32;
    constexpr int NPI  = 2;
    constexpr int NNI  = 4;

    extern __shared__ __align__(16) char smem[];
    const uint32_t sb = s2u(smem);
    const int tid  = threadIdx.x;
    const int warp = tid >> 5, lane = tid & 31;
    const int wm = warp & 3, wn = warp >> 2;
    const int bm = blockIdx.y * 128, bn = blockIdx.x * 64;

    float acc[2][NNI][4];
    #pragma unroll
    for (int i = 0; i < 2; i++)
        #pragma unroll
        for (int j = 0; j < NNI; j++)
            #pragma unroll
            for (int l = 0; l < 4; l++) acc[i][j][l] = 0.0f;

    const int a_r = (lane & 7) + ((lane >> 3) & 1) * 8;
    const int a_c = ((lane >> 4) & 1) * 8;
    const int b_r = (lane & 7) + ((lane >> 4) & 1) * 8;
    const int b_c = ((lane >> 3) & 1) * 8;

    const int nch = K >> 5;

    auto load_stage = [&](int st, int k0) {
        uint32_t base = sb + st*STAGE;
        #pragma unroll
        for (int c = tid; c < 512; c += 256) {
            int row = c >> 2, seg = c & 3;
            CPA(base + row*80 + seg*16, A + (size_t)(bm + row)*K + k0 + seg*8);
        }
        {
            int row = tid >> 2, seg = tid & 3;
            CPA(base + 10240 + row*80 + seg*16, W + (size_t)(bn + row)*K + k0 + seg*8);
        }
        CPA_COMMIT();
    };

    // prologue: stages 0 and 1
    load_stage(0, 0);
    if (nch > 1) load_stage(1, 32);

    int st = 0;
    for (int c = 0; c < nch; c++) {
        CPA_WAIT1();
        __syncthreads();
        if (c + 2 < nch) {
            int st2 = st + 2; if (st2 >= NSTG) st2 -= NSTG;
            load_stage(st2, (c + 2) << 5);
        }

        const uint32_t base = sb + st*STAGE;
        #pragma unroll
        for (int ks = 0; ks < 2; ks++) {
            uint32_t ah[2][4];
            #pragma unroll
            for (int mi = 0; mi < 2; mi++) {
                uint32_t off = base + ((wm*32 + mi*16 + a_r)*PADH + ks*16 + a_c) * 2;
                ldsm4(ah[mi], off);
            }
            uint32_t bh[NNI][2];
            #pragma unroll
            for (int pi = 0; pi < NPI; pi++) {
                uint32_t off = base + 10240 + ((wn*WNT + pi*16 + b_r)*PADH + ks*16 + b_c) * 2;
                uint32_t t[4];
                ldsm4(t, off);
                bh[2*pi][0]=t[0]; bh[2*pi][1]=t[1]; bh[2*pi+1][0]=t[2]; bh[2*pi+1][1]=t[3];
            }
            #pragma unroll
            for (int ni = 0; ni < NNI; ni++)
                #pragma unroll
                for (int mi = 0; mi < 2; mi++)
                    mma16816(acc[mi][ni], ah[mi], bh[ni]);
        }
        st++; if (st >= NSTG) st = 0;
    }

    const int gr = lane >> 2, gc = (lane & 3) * 2;
    #pragma unroll
    for (int mi = 0; mi < 2; mi++) {
        #pragma unroll
        for (int ni = 0; ni < NNI; ni++) {
            int r0 = bm + wm*32 + mi*16 + gr;
            int cc = bn + wn*WNT + ni*8 + gc;
            float2 v0 = make_float2(acc[mi][ni][0], acc[mi][ni][1]);
            float2 v1 = make_float2(acc[mi][ni][2], acc[mi][ni][3]);
            if (EPI != 3 && bias) {
                float2 bz = *reinterpret_cast<const float2*>(bias + cc);
                v0.x += bz.x; v0.y += bz.y; v1.x += bz.x; v1.y += bz.y;
            }
            if (EPI == 1) {
                float2 r0v = *reinterpret_cast<const float2*>(res + (size_t)r0*N + cc);
                float2 r1v = *reinterpret_cast<const float2*>(res + (size_t)(r0+8)*N + cc);
                v0.x += r0v.x; v0.y += r0v.y; v1.x += r1v.x; v1.y += r1v.y;
            }
            if (EPI == 2) {
                v0.x = 0.5f*v0.x*(1.0f + erff(v0.x*0.7071067811865475f));
                v0.y = 0.5f*v0.y*(1.0f + erff(v0.y*0.7071067811865475f));
                v1.x = 0.5f*v1.x*(1.0f + erff(v1.x*0.7071067811865475f));
                v1.y = 0.5f*v1.y*(1.0f + erff(v1.y*0.7071067811865475f));
            }
            if (EPI == 3) {
                if (cc < 256) {          // MQ: fp32, stride 256
                    *reinterpret_cast<float2*>(C + (size_t)r0*256 + cc)     = v0;
                    *reinterpret_cast<float2*>(C + (size_t)(r0+8)*256 + cc) = v1;
                } else if (cc < 384) {   // CD: fp16, stride 128
                    int c2 = cc - 256;
                    __half2 h0; h0.x = __float2half_rn(v0.x); h0.y = __float2half_rn(v0.y);
                    __half2 h1; h1.x = __float2half_rn(v1.x); h1.y = __float2half_rn(v1.y);
                    *reinterpret_cast<__half2*>(Ch + (size_t)r0*128 + c2)     = h0;
                    *reinterpret_cast<__half2*>(Ch + (size_t)(r0+8)*128 + c2) = h1;
                } else {                 // IQK: fp32, stride 64
                    int c2 = cc - 384;
                    *reinterpret_cast<float2*>(C2 + (size_t)r0*64 + c2)     = v0;
                    *reinterpret_cast<float2*>(C2 + (size_t)(r0+8)*64 + c2) = v1;
                }
            } else if (OHALF) {
                __half2 h0; h0.x = __float2half_rn(v0.x); h0.y = __float2half_rn(v0.y);
                __half2 h1; h1.x = __float2half_rn(v1.x); h1.y = __float2half_rn(v1.y);
                *reinterpret_cast<__half2*>(Ch + (size_t)r0*N + cc)     = h0;
                *reinterpret_cast<__half2*>(Ch + (size_t)(r0+8)*N + cc) = h1;
            } else {
                *reinterpret_cast<float2*>(C + (size_t)r0*N + cc)     = v0;
                *reinterpret_cast<float2*>(C + (size_t)(r0+8)*N + cc) = v1;
            }
        }
    }
}

// ---------------- feature attention over C=4 tokens (fp16 output) ----------------
__global__ void feat_attn(const float* __restrict__ QKV, __half* __restrict__ AOh) {
    int s = blockIdx.x;
    int h = threadIdx.x >> 5;
    int lane = threadIdx.x & 31;
    float q[4], k[4], v[4];
    #pragma unroll
    for (int c = 0; c < 4; c++) {
        const float* row = QKV + (size_t)(s*4 + c) * 768;
        q[c] = row[h*32 + lane];
        k[c] = row[256 + h*32 + lane];
        v[c] = row[512 + h*32 + lane];
    }
    float sc[4][4];
    #pragma unroll
    for (int a = 0; a < 4; a++)
        #pragma unroll
        for (int b = 0; b < 4; b++) {
            float p = q[a] * k[b];
            #pragma unroll
            for (int o = 16; o > 0; o >>= 1) p += __shfl_xor_sync(0xffffffffu, p, o);
            sc[a][b] = p * 0.17677669529663687f;
        }
    #pragma unroll
    for (int a = 0; a < 4; a++) {
        float mx = fmaxf(fmaxf(sc[a][0], sc[a][1]), fmaxf(sc[a][2], sc[a][3]));
        float e0 = expf(sc[a][0]-mx), e1 = expf(sc[a][1]-mx);
        float e2 = expf(sc[a][2]-mx), e3 = expf(sc[a][3]-mx);
        float den = e0 + e1 + e2 + e3;
        float o = (e0*v[0] + e1*v[1] + e2*v[2] + e3*v[3]) / den;
        AOh[(size_t)(s*4 + a)*256 + h*32 + lane] = __float2half_rn(o);
    }
}

// ---------------- layernorm, warp-per-token, layout remap, optional fp16 out ----------------
__global__ void ln_kernel(const float* __restrict__ X, const float* __restrict__ g,
                          const float* __restrict__ b, float* __restrict__ Y,
                          __half* __restrict__ Yh, int mode) {
    int t = blockIdx.x * 8 + (threadIdx.x >> 5);
    int lane = threadIdx.x & 31;
    const float* xr = X + (size_t)t * 256 + lane * 8;
    float4 x0 = *reinterpret_cast<const float4*>(xr);
    float4 x1 = *reinterpret_cast<const float4*>(xr + 4);
    float s = x0.x + x0.y + x0.z + x0.w + x1.x + x1.y + x1.z + x1.w;
    #pragma unroll
    for (int o = 16; o > 0; o >>= 1) s += __shfl_xor_sync(0xffffffffu, s, o);
    float m = s * (1.0f / 256.0f);
    float d[8] = {x0.x-m, x0.y-m, x0.z-m, x0.w-m, x1.x-m, x1.y-m, x1.z-m, x1.w-m};
    float vs = 0.f;
    #pragma unroll
    for (int i = 0; i < 8; i++) vs += d[i]*d[i];
    #pragma unroll
    for (int o = 16; o > 0; o >>= 1) vs += __shfl_xor_sync(0xffffffffu, vs, o);
    float inv = rsqrtf(vs * (1.0f/256.0f) + 1e-5f);
    float y[8];
    const float* gp = g + lane*8;
    const float* bp = b + lane*8;
    #pragma unroll
    for (int i = 0; i < 8; i++) y[i] = d[i]*inv*gp[i] + bp[i];
    int ot;
    if (mode == 0) ot = t;
    else if (mode == 1) { int bb = t >> 12, r = (t >> 2) & 1023, c = t & 3; ot = ((bb<<2)|c)*1024 + r; }
    else { int bf = t >> 10, r = t & 1023; int bb = bf >> 2, c = bf & 3; ot = bb*4096 + r*4 + c; }
    float* yr = Y + (size_t)ot * 256 + lane * 8;
    *reinterpret_cast<float4*>(yr)     = make_float4(y[0], y[1], y[2], y[3]);
    *reinterpret_cast<float4*>(yr + 4) = make_float4(y[4], y[5], y[6], y[7]);
    if (Yh) {
        size_t o2 = (size_t)ot * 256 + lane * 8;
        #pragma unroll
        for (int i = 0; i < 4; i++) {
            __half2 h;
            h.x = __float2half_rn(y[2*i]); h.y = __float2half_rn(y[2*i+1]);
            *reinterpret_cast<__half2*>(Yh + o2 + 2*i) = h;
        }
    }
}

// ---------------- indexer: scales / quantize / score+topk ----------------
__global__ void idx_scales(const float* __restrict__ IQK, float* __restrict__ SC) {
    int bf = blockIdx.x, h = blockIdx.y, kind = blockIdx.z;
    int r0 = (kind == 1) ? SPLIT : 0;
    int r1 = (kind == 1) ? 1024 : SPLIT;
    int cb = (kind == 2) ? 32 : 0;
    int n = (r1 - r0) * 8;
    float m = 0.0f;
    for (int i = threadIdx.x; i < n; i += 256) {
        int r = r0 + (i >> 3), d = i & 7;
        m = fmaxf(m, fabsf(IQK[(size_t)(bf*1024 + r)*64 + cb + h*8 + d]));
    }
    __shared__ float sm[8];
    #pragma unroll
    for (int o = 16; o > 0; o >>= 1) m = fmaxf(m, __shfl_xor_sync(0xffffffffu, m, o));
    if ((threadIdx.x & 31) == 0) sm[threadIdx.x >> 5] = m;
    __syncthreads();
    if (threadIdx.x == 0) {
        float mm = sm[0];
        for (int i = 1; i < 8; i++) mm = fmaxf(mm, sm[i]);
        SC[kind*32 + bf*4 + h] = (mm + 1e-6f) / 127.0f;
    }
}

__global__ void idx_quant(const float* __restrict__ IQK, const float* __restrict__ SC,
                          int* __restrict__ QI, int* __restrict__ KI) {
    int idx = blockIdx.x * 256 + threadIdx.x;
    if (idx >= NTOK*32) return;
    int t = idx >> 5, j = idx & 31, h = j >> 3;
    int bf = t >> 10, r = t & 1023;
    char* qb = (char*)QI;
    char* kb = (char*)KI;
    float qs = SC[(r < SPLIT ? 0 : 1)*32 + bf*4 + h];
    float qv = rintf(IQK[(size_t)t*64 + j] / qs);
    qv = fminf(fmaxf(qv, -127.0f), 127.0f);
    qb[idx] = (char)(int)qv;
    if (r < SPLIT) {
        float ks = SC[64 + bf*4 + h];
        float kv = rintf(IQK[(size_t)t*64 + 32 + j] / ks);
        kv = fminf(fmaxf(kv, -127.0f), 127.0f);
        kb[idx] = (char)(int)kv;
    } else {
        kb[idx] = 0;
    }
}

// warp-per-token top-k: scores in 24 regs/lane, 32 argmax rounds, no block barriers
__global__ void idx_topk(const int* __restrict__ QI, const int* __restrict__ KI,
                         const float* __restrict__ SC, const float* __restrict__ ow,
                         int* __restrict__ IDX) {
    int warp = threadIdx.x >> 5, lane = threadIdx.x & 31;
    int t = blockIdx.x * 8 + warp;
    int bf = t >> 10, r = t & 1023;

    int4 q0 = *reinterpret_cast<const int4*>(QI + (size_t)t*8);
    int4 q1 = *reinterpret_cast<const int4*>(QI + (size_t)t*8 + 4);
    int qw[8] = {q0.x, q0.y, q0.z, q0.w, q1.x, q1.y, q1.z, q1.w};

    float ssc[4], sow[4];
    #pragma unroll
    for (int h = 0; h < 4; h++) {
        float qs = SC[(r < SPLIT ? 0 : 1)*32 + bf*4 + h];
        ssc[h] = qs * SC[64 + bf*4 + h];
        sow[h] = ow[h];
    }

    float rv[24];
    #pragma unroll
    for (int i = 0; i < 24; i++) {
        int k = i*32 + lane;
        const int* kw = KI + (size_t)(bf*1024 + k)*8;
        int4 k0 = *reinterpret_cast<const int4*>(kw);
        int4 k1 = *reinterpret_cast<const int4*>(kw + 4);
        int kwv[8] = {k0.x, k0.y, k0.z, k0.w, k1.x, k1.y, k1.z, k1.w};
        float acc = 0.f;
        #pragma unroll
        for (int h = 0; h < 4; h++) {
            int d = __dp4a(qw[2*h], kwv[2*h], __dp4a(qw[2*h+1], kwv[2*h+1], 0));
            acc += fmaxf((float)d * ssc[h], 0.0f) * sow[h];
        }
        rv[i] = acc;
    }

    for (int sel = 0; sel < TOPK_; sel++) {
        float bv = -FLT_MAX; int bi = 0x7fffffff;
        #pragma unroll
        for (int i = 0; i < 24; i++) {
            if (rv[i] > bv) { bv = rv[i]; bi = i*32 + lane; }
        }
        #pragma unroll
        for (int o = 16; o > 0; o >>= 1) {
            float ov = __shfl_xor_sync(0xffffffffu, bv, o);
            int   oi = __shfl_xor_sync(0xffffffffu, bi, o);
            if (ov > bv || (ov == bv && oi < bi)) { bv = ov; bi = oi; }
        }
        if (lane == 0) IDX[t*TOPK_ + sel] = bi;
        if ((bi & 31) == lane) rv[bi >> 5] = -FLT_MAX;
    }
}

// ---------------- sparse MLA attention v2: smem-staged, shuffle-light ----------------
__global__ void mla_attn(const float* __restrict__ MQ, const float* __restrict__ KV,
                         const int* __restrict__ IDX, __half* __restrict__ AO2h) {
    __shared__ float sBuf[8][32][33];
    __shared__ float sQ[8][32];
    __shared__ float sW[8][32];
    __shared__ int sidx[32];

    int t = blockIdx.x;
    int bf = t >> 10;
    int h = threadIdx.x >> 5, lane = threadIdx.x & 31;

    if (threadIdx.x < 32) sidx[threadIdx.x] = IDX[t*TOPK_ + threadIdx.x];
    float q = MQ[(size_t)t*256 + h*32 + lane];
    sQ[h][lane] = q;
    __syncthreads();

    #pragma unroll 4
    for (int j = 0; j < 32; j++) {
        int kt = bf*1024 + sidx[j];
        sBuf[h][j][lane] = KV[(size_t)kt*512 + h*32 + lane];
    }
    __syncwarp();

    float score = 0.0f;
    #pragma unroll
    for (int d = 0; d < 32; d++)
        score += sQ[h][d] * sBuf[h][lane][d];
    score *= 0.17677669529663687f;

    float mx = score;
    #pragma unroll
    for (int o = 16; o > 0; o >>= 1) mx = fmaxf(mx, __shfl_xor_sync(0xffffffffu, mx, o));
    float e = expf(score - mx);
    float ssum = e;
    #pragma unroll
    for (int o = 16; o > 0; o >>= 1) ssum += __shfl_xor_sync(0xffffffffu, ssum, o);
    sW[h][lane] = e / ssum;
    __syncwarp();

    #pragma unroll 4
    for (int j = 0; j < 32; j++) {
        int kt = bf*1024 + sidx[j];
        sBuf[h][j][lane] = KV[(size_t)kt*512 + 256 + h*32 + lane];
    }
    __syncwarp();

    float acc = 0.0f;
    #pragma unroll
    for (int j = 0; j < 32; j++)
        acc += sW[h][j] * sBuf[h][j][lane];

    AO2h[(size_t)t*256 + h*32 + lane] = __float2half_rn(acc);
}

// ---------------- host launcher ----------------
static float* symF(const void* sym) { void* p = nullptr; cudaGetSymbolAddress(&p, sym); return (float*)p; }
static int*   symI(const void* sym) { void* p = nullptr; cudaGetSymbolAddress(&p, sym); return (int*)p; }
static __half* symH(const void* sym) { void* p = nullptr; cudaGetSymbolAddress(&p, sym); return (__half*)p; }

extern "C" void kernel_launch(void* const* d_in, const int* in_sizes, int n_in,
                              void* d_out, int out_size) {
    (void)in_sizes; (void)n_in; (void)out_size;
    const float* src      = (const float*)d_in[0];
    const float* fa_in_w  = (const float*)d_in[2];
    const float* fa_in_b  = (const float*)d_in[3];
    const float* fa_out_w = (const float*)d_in[4];
    const float* fa_out_b = (const float*)d_in[5];
    const float* n1g = (const float*)d_in[6];
    const float* n1b = (const float*)d_in[7];
    const float* iqw = (const float*)d_in[8];
    const float* ikw = (const float*)d_in[9];
    const float* iow = (const float*)d_in[10];
    const float* mqw = (const float*)d_in[11];
    const float* mdw = (const float*)d_in[12];
    const float* muw = (const float*)d_in[13];
    const float* mow = (const float*)d_in[14];
    const float* n2g = (const float*)d_in[15];
    const float* n2b = (const float*)d_in[16];
    const float* l1w = (const float*)d_in[17];
    const float* l1b = (const float*)d_in[18];
    const float* l2w = (const float*)d_in[19];
    const float* l2b = (const float*)d_in[20];
    const float* n3g = (const float*)d_in[21];
    const float* n3b = (const float*)d_in[22];

    float* QKV = symF(g_QKV); float* X   = symF(g_X);   float* ST  = symF(g_ST);
    float* IQK = symF(g_IQK); float* SC  = symF(g_SC);
    int*   QI  = symI(g_QI);  int*   KI  = symI(g_KI);  int*   IDX = symI(g_IDX);
    float* MQ  = symF(g_MQ);  float* KV  = symF(g_KV);  float* ST2 = symF(g_ST2);
    float* X2  = symF(g_X2);  float* X3  = symF(g_X3);
    __half *SRCh=symH(g_SRCh);
    __half *AOh=symH(g_AOh);
    __half *STh=symH(g_STh);
    __half *CDh=symH(g_CDh);
    __half *AO2h=symH(g_AO2h);
    __half *X2h=symH(g_X2h);
    __half *H1h=symH(g_H1h);
    __half *Wp=symH(g_W);

    static cudaStream_t sW = nullptr, sB = nullptr;
    static cudaEvent_t evRoot = nullptr, evFA = nullptr, evW = nullptr, ev1 = nullptr, evB = nullptr;
    if (!sW) {
        cudaStreamCreateWithFlags(&sW, cudaStreamNonBlocking);
        cudaStreamCreateWithFlags(&sB, cudaStreamNonBlocking);
        cudaEventCreateWithFlags(&evRoot, cudaEventDisableTiming);
        cudaEventCreateWithFlags(&evFA,  cudaEventDisableTiming);
        cudaEventCreateWithFlags(&evW,   cudaEventDisableTiming);
        cudaEventCreateWithFlags(&ev1,   cudaEventDisableTiming);
        cudaEventCreateWithFlags(&evB,   cudaEventDisableTiming);
        cudaFuncSetAttribute(hgemm<0,0>, cudaFuncAttributeMaxDynamicSharedMemorySize, 46080);
        cudaFuncSetAttribute(hgemm<1,0>, cudaFuncAttributeMaxDynamicSharedMemorySize, 46080);
        cudaFuncSetAttribute(hgemm<2,1>, cudaFuncAttributeMaxDynamicSharedMemorySize, 46080);
        cudaFuncSetAttribute(hgemm<3,0>, cudaFuncAttributeMaxDynamicSharedMemorySize, 46080);
    }

    dim3 blk(256);

    // Fork: weight conversions on side stream, overlapping src conversion / Stage A
    cudaEventRecord(evRoot, 0);
    cudaStreamWaitEvent(sW, evRoot, 0);
    wcvt_fa<<<256, blk, 0, sW>>>(fa_in_w, fa_out_w, Wp);
    cudaEventRecord(evFA, sW);
    wcvt6<<<752, blk, 0, sW>>>(mqw, mdw, muw, mow, l1w, l2w, iqw, ikw, Wp);
    cudaEventRecord(evW, sW);

    // Stage A (main stream)
    cvt_h<<<2048, blk>>>(src, SRCh, NTOK*256);
    cudaStreamWaitEvent(0, evFA, 0);
    hgemm<0,0><<<dim3(12,64), blk, 46080>>>(SRCh, Wp+W_FAIN,
        fa_in_b, nullptr, QKV, nullptr, nullptr, NTOK, 768, 256);
    feat_attn<<<2048, blk>>>(QKV, AOh);
    hgemm<1,0><<<dim3(4,64), blk, 46080>>>(AOh, Wp+W_FAOUT,
        fa_out_b, src, X, nullptr, nullptr, NTOK, 256, 256);
    ln_kernel<<<NTOK/8, blk>>>(X, n1g, n1b, ST, STh, 1);

    // Merged MQ(fp32) + MD(fp16) + IDX(fp32) GEMM, N=448
    cudaStreamWaitEvent(0, evW, 0);
    hgemm<3,0><<<dim3(7,64), blk, 46080>>>(STh, Wp+W_MQ,
        nullptr, nullptr, MQ, CDh, IQK, NTOK, 448, 256);

    // Fork indexer branch (scales/quant/topk)
    cudaEventRecord(ev1, 0);
    cudaStreamWaitEvent(sB, ev1, 0);
    idx_scales<<<dim3(8,4,3), blk, 0, sB>>>(IQK, SC);
    idx_quant<<<NTOK*32/256, blk, 0, sB>>>(IQK, SC, QI, KI);
    idx_topk<<<NTOK/8, blk, 0, sB>>>(QI, KI, SC, iow, IDX);
    cudaEventRecord(evB, sB);

    // Stage C (main, concurrent with indexer branch)
    hgemm<0,0><<<dim3(8,64), blk, 46080>>>(CDh, Wp+W_MU,
        nullptr, nullptr, KV, nullptr, nullptr, NTOK, 512, 128);

    // Join + attention
    cudaStreamWaitEvent(0, evB, 0);
    mla_attn<<<NTOK, blk>>>(MQ, KV, IDX, AO2h);
    hgemm<1,0><<<dim3(4,64), blk, 46080>>>(AO2h, Wp+W_MO,
        nullptr, ST, ST2, nullptr, nullptr, NTOK, 256, 256);

    // Stage D
    ln_kernel<<<NTOK/8, blk>>>(ST2, n2g, n2b, X2, X2h, 2);
    hgemm<2,1><<<dim3(16,64), blk, 46080>>>(X2h, Wp+W_L1,
        l1b, nullptr, nullptr, H1h, nullptr, NTOK, 1024, 256);
    hgemm<1,0><<<dim3(4,64), blk, 46080>>>(H1h, Wp+W_L2,
        l2b, X2, X3, nullptr, nullptr, NTOK, 256, 1024);
    ln_kernel<<<NTOK/8, blk>>>(X3, n3g, n3b, (float*)d_out, nullptr, 0);
}

// round 16
// speedup vs baseline: 1.2163x; 1.0234x over previous
#include <cuda_runtime.h>
#include <cuda_fp16.h>
#include <math.h>
#include <float.h>
#include <stdint.h>

// ---------------- problem constants ----------------
#define NTOK   8192          // B*R*C tokens = 2*1024*4
#define EDIM   256
#define SPLIT  768
#define TOPK_  32
#define LATD   128
#define MLPD   1024

// ---------------- device scratch (no allocs allowed) ----------------
__device__ float g_QKV[NTOK*768];
__device__ float g_X  [NTOK*EDIM];
__device__ float g_ST [NTOK*EDIM];
__device__ float g_IQK[NTOK*64];
__device__ float g_SC [3*32];
__device__ int   g_QI [NTOK*8];
__device__ int   g_KI [NTOK*8];
__device__ int   g_IDX[NTOK*TOPK_];
__device__ float g_MQ [NTOK*EDIM];
__device__ float g_KV [NTOK*2*EDIM];
__device__ float g_ST2[NTOK*EDIM];
__device__ float g_X2 [NTOK*EDIM];
__device__ float g_X3 [NTOK*EDIM];
// fp16 activation buffers + weights
__device__ __half g_SRCh[NTOK*EDIM];
__device__ __half g_AOh [NTOK*EDIM];
__device__ __half g_STh [NTOK*EDIM];
__device__ __half g_CDh [NTOK*LATD];
__device__ __half g_AO2h[NTOK*EDIM];
__device__ __half g_X2h [NTOK*EDIM];
__device__ __half g_H1h [NTOK*MLPD];
__device__ __half g_W   [1<<20];

// weight offsets inside g_W (idx rows packed right after MD for merged N=448 GEMM)
#define W_FAIN  0
#define W_FAOUT 196608
#define W_MQ    262144
#define W_MD    327680
#define W_IDX   360448
#define W_MU    376832
#define W_MO    442368
#define W_L1    507904
#define W_L2    770048

// ---------------- helpers ----------------
__device__ __forceinline__ uint32_t s2u(const void* p) {
    uint32_t a;
    asm("{ .reg .u64 t; cvta.to.shared.u64 t, %1; cvt.u32.u64 %0, t; }" : "=r"(a) : "l"(p));
    return a;
}
__device__ __forceinline__ void ldsm4(uint32_t* r, uint32_t addr) {
    asm volatile("ldmatrix.sync.aligned.m8n8.x4.shared.b16 {%0,%1,%2,%3}, [%4];"
                 : "=r"(r[0]), "=r"(r[1]), "=r"(r[2]), "=r"(r[3]) : "r"(addr));
}
__device__ __forceinline__ void mma16816(float* d, const uint32_t* a, const uint32_t* b) {
    asm volatile("mma.sync.aligned.m16n8k16.row.col.f32.f16.f16.f32 "
                 "{%0,%1,%2,%3}, {%4,%5,%6,%7}, {%8,%9}, {%0,%1,%2,%3};"
                 : "+f"(d[0]), "+f"(d[1]), "+f"(d[2]), "+f"(d[3])
                 : "r"(a[0]), "r"(a[1]), "r"(a[2]), "r"(a[3]), "r"(b[0]), "r"(b[1]));
}
#define CPA(dst, src) asm volatile("cp.async.cg.shared.global [%0], [%1], 16;" :: "r"(dst), "l"(src))
#define CPA_COMMIT()  asm volatile("cp.async.commit_group;" ::: "memory")
#define CPA_WAIT1()   asm volatile("cp.async.wait_group 1;" ::: "memory")
#define CPA_WAIT0()   asm volatile("cp.async.wait_group 0;" ::: "memory")

__device__ __forceinline__ void cvt4h(const float* __restrict__ x, __half* __restrict__ h, int i) {
    float4 v = *reinterpret_cast<const float4*>(x + i);
    __half2 h0; h0.x = __float2half_rn(v.x); h0.y = __float2half_rn(v.y);
    __half2 h1; h1.x = __float2half_rn(v.z); h1.y = __float2half_rn(v.w);
    *reinterpret_cast<__half2*>(h + i)     = h0;
    *reinterpret_cast<__half2*>(h + i + 2) = h1;
}

// ---------------- conversions ----------------
__global__ void cvt_h(const float* __restrict__ x, __half* __restrict__ h, int n) {
    int i = (blockIdx.x * 256 + threadIdx.x) * 4;
    if (i < n) cvt4h(x, h, i);
}

__global__ void wcvt_fa(const float* __restrict__ fin, const float* __restrict__ fout,
                        __half* __restrict__ W) {
    int b = blockIdx.x;
    const float* src; int dst, rel;
    if (b < 192) { src = fin;  dst = W_FAIN;  rel = b; }
    else         { src = fout; dst = W_FAOUT; rel = b - 192; }
    int i = (rel*256 + threadIdx.x)*4;
    cvt4h(src, W + dst, i);
}

__global__ void wcvt6(const float* __restrict__ mq, const float* __restrict__ md,
                      const float* __restrict__ mu, const float* __restrict__ mo,
                      const float* __restrict__ l1, const float* __restrict__ l2,
                      const float* __restrict__ iq, const float* __restrict__ ik,
                      __half* __restrict__ W) {
    int b = blockIdx.x;
    const float* src; int dst, rel;
    if (b < 64)       { src = mq; dst = W_MQ;        rel = b; }
    else if (b < 96)  { src = md; dst = W_MD;        rel = b-64; }
    else if (b < 104) { src = iq; dst = W_IDX;       rel = b-96; }
    else if (b < 112) { src = ik; dst = W_IDX+8192;  rel = b-104; }
    else if (b < 176) { src = mu; dst = W_MU;        rel = b-112; }
    else if (b < 240) { src = mo; dst = W_MO;        rel = b-176; }
    else if (b < 496) { src = l1; dst = W_L1;        rel = b-240; }
    else              { src = l2; dst = W_L2;        rel = b-496; }
    int i = (rel*256 + threadIdx.x)*4;
    cvt4h(src, W + dst, i);
}

// ---------------- HMMA fp16 GEMM, BM=128, BN=64, BK=64, 2-stage, 3 CTA/SM ----
// D = A*W (both fp16, fp32 accum).
// EPI: 0 +bias(opt); 1 +bias(opt)+res; 2 gelu(acc+bias) fp16-out; 3 MQ/CD/IQK mixed
#define PADH 72        // halves per smem row (144B stride; 144 mod 128 = 16 -> conflict-free ldsm)
#define ASTG (128*PADH*2)          // 18432 B
#define STAGE (ASTG + 64*PADH*2)   // 27648 B
#define SMEMTOT (2*STAGE)          // 55296 B

template<int EPI, int OHALF>
__global__ void __launch_bounds__(256, 3)
hgemm(const __half* __restrict__ A, const __half* __restrict__ W,
      const float* __restrict__ bias, const float* __restrict__ res,
      float* __restrict__ C, __half* __restrict__ Ch, float* __restrict__ C2,
      int M, int N, int K) {
    constexpr int WNT  = 32;
    constexpr int NPI  = 2;
    constexpr int NNI  = 4;

    extern __shared__ __align__(16) char smem[];
    const uint32_t sb = s2u(smem);
    const int tid  = threadIdx.x;
    const int warp = tid >> 5, lane = tid & 31;
    const int wm = warp & 3, wn = warp >> 2;
    const int bm = blockIdx.y * 128, bn = blockIdx.x * 64;

    float acc[2][NNI][4];
    #pragma unroll
    for (int i = 0; i < 2; i++)
        #pragma unroll
        for (int j = 0; j < NNI; j++)
            #pragma unroll
            for (int l = 0; l < 4; l++) acc[i][j][l] = 0.0f;

    const int a_r = (lane & 7) + ((lane >> 3) & 1) * 8;
    const int a_c = ((lane >> 4) & 1) * 8;
    const int b_r = (lane & 7) + ((lane >> 4) & 1) * 8;
    const int b_c = ((lane >> 3) & 1) * 8;

    const int nch = K >> 6;   // 64-wide chunks

    auto load_stage = [&](int st, int k0) {
        uint32_t base = sb + st*STAGE;
        // A: 128 rows x 64 halves (128B) = 8 segs of 16B per row -> 1024 CPAs / 256 thr = 4 each
        #pragma unroll
        for (int c = tid; c < 1024; c += 256) {
            int row = c >> 3, seg = c & 7;
            CPA(base + row*144 + seg*16, A + (size_t)(bm + row)*K + k0 + seg*8);
        }
        // B: 64 rows x 64 halves -> 512 CPAs / 256 thr = 2 each
        #pragma unroll
        for (int c = tid; c < 512; c += 256) {
            int row = c >> 3, seg = c & 7;
            CPA(base + ASTG + row*144 + seg*16, W + (size_t)(bn + row)*K + k0 + seg*8);
        }
        CPA_COMMIT();
    };

    load_stage(0, 0);

    for (int c = 0; c < nch; c++) {
        if (c + 1 < nch) { load_stage((c+1) & 1, (c+1) << 6); CPA_WAIT1(); }
        else             { CPA_WAIT0(); }
        __syncthreads();

        const uint32_t base = sb + (c & 1)*STAGE;
        #pragma unroll
        for (int ks = 0; ks < 4; ks++) {
            uint32_t ah[2][4];
            #pragma unroll
            for (int mi = 0; mi < 2; mi++) {
                uint32_t off = base + ((wm*32 + mi*16 + a_r)*PADH + ks*16 + a_c) * 2;
                ldsm4(ah[mi], off);
            }
            uint32_t bh[NNI][2];
            #pragma unroll
            for (int pi = 0; pi < NPI; pi++) {
                uint32_t off = base + ASTG + ((wn*WNT + pi*16 + b_r)*PADH + ks*16 + b_c) * 2;
                uint32_t t[4];
                ldsm4(t, off);
                bh[2*pi][0]=t[0]; bh[2*pi][1]=t[1]; bh[2*pi+1][0]=t[2]; bh[2*pi+1][1]=t[3];
            }
            #pragma unroll
            for (int ni = 0; ni < NNI; ni++)
                #pragma unroll
                for (int mi = 0; mi < 2; mi++)
                    mma16816(acc[mi][ni], ah[mi], bh[ni]);
        }
        __syncthreads();
    }

    const int gr = lane >> 2, gc = (lane & 3) * 2;
    #pragma unroll
    for (int mi = 0; mi < 2; mi++) {
        #pragma unroll
        for (int ni = 0; ni < NNI; ni++) {
            int r0 = bm + wm*32 + mi*16 + gr;
            int cc = bn + wn*WNT + ni*8 + gc;
            float2 v0 = make_float2(acc[mi][ni][0], acc[mi][ni][1]);
            float2 v1 = make_float2(acc[mi][ni][2], acc[mi][ni][3]);
            if (EPI != 3 && bias) {
                float2 bz = *reinterpret_cast<const float2*>(bias + cc);
                v0.x += bz.x; v0.y += bz.y; v1.x += bz.x; v1.y += bz.y;
            }
            if (EPI == 1) {
                float2 r0v = *reinterpret_cast<const float2*>(res + (size_t)r0*N + cc);
                float2 r1v = *reinterpret_cast<const float2*>(res + (size_t)(r0+8)*N + cc);
                v0.x += r0v.x; v0.y += r0v.y; v1.x += r1v.x; v1.y += r1v.y;
            }
            if (EPI == 2) {
                v0.x = 0.5f*v0.x*(1.0f + erff(v0.x*0.7071067811865475f));
                v0.y = 0.5f*v0.y*(1.0f + erff(v0.y*0.7071067811865475f));
                v1.x = 0.5f*v1.x*(1.0f + erff(v1.x*0.7071067811865475f));
                v1.y = 0.5f*v1.y*(1.0f + erff(v1.y*0.7071067811865475f));
            }
            if (EPI == 3) {
                if (cc < 256) {          // MQ: fp32, stride 256
                    *reinterpret_cast<float2*>(C + (size_t)r0*256 + cc)     = v0;
                    *reinterpret_cast<float2*>(C + (size_t)(r0+8)*256 + cc) = v1;
                } else if (cc < 384) {   // CD: fp16, stride 128
                    int c2 = cc - 256;
                    __half2 h0; h0.x = __float2half_rn(v0.x); h0.y = __float2half_rn(v0.y);
                    __half2 h1; h1.x = __float2half_rn(v1.x); h1.y = __float2half_rn(v1.y);
                    *reinterpret_cast<__half2*>(Ch + (size_t)r0*128 + c2)     = h0;
                    *reinterpret_cast<__half2*>(Ch + (size_t)(r0+8)*128 + c2) = h1;
                } else {                 // IQK: fp32, stride 64
                    int c2 = cc - 384;
                    *reinterpret_cast<float2*>(C2 + (size_t)r0*64 + c2)     = v0;
                    *reinterpret_cast<float2*>(C2 + (size_t)(r0+8)*64 + c2) = v1;
                }
            } else if (OHALF) {
                __half2 h0; h0.x = __float2half_rn(v0.x); h0.y = __float2half_rn(v0.y);
                __half2 h1; h1.x = __float2half_rn(v1.x); h1.y = __float2half_rn(v1.y);
                *reinterpret_cast<__half2*>(Ch + (size_t)r0*N + cc)     = h0;
                *reinterpret_cast<__half2*>(Ch + (size_t)(r0+8)*N + cc) = h1;
            } else {
                *reinterpret_cast<float2*>(C + (size_t)r0*N + cc)     = v0;
                *reinterpret_cast<float2*>(C + (size_t)(r0+8)*N + cc) = v1;
            }
        }
    }
}

// ---------------- feature attention over C=4 tokens (fp16 output) ----------------
__global__ void feat_attn(const float* __restrict__ QKV, __half* __restrict__ AOh) {
    int s = blockIdx.x;
    int h = threadIdx.x >> 5;
    int lane = threadIdx.x & 31;
    float q[4], k[4], v[4];
    #pragma unroll
    for (int c = 0; c < 4; c++) {
        const float* row = QKV + (size_t)(s*4 + c) * 768;
        q[c] = row[h*32 + lane];
        k[c] = row[256 + h*32 + lane];
        v[c] = row[512 + h*32 + lane];
    }
    float sc[4][4];
    #pragma unroll
    for (int a = 0; a < 4; a++)
        #pragma unroll
        for (int b = 0; b < 4; b++) {
            float p = q[a] * k[b];
            #pragma unroll
            for (int o = 16; o > 0; o >>= 1) p += __shfl_xor_sync(0xffffffffu, p, o);
            sc[a][b] = p * 0.17677669529663687f;
        }
    #pragma unroll
    for (int a = 0; a < 4; a++) {
        float mx = fmaxf(fmaxf(sc[a][0], sc[a][1]), fmaxf(sc[a][2], sc[a][3]));
        float e0 = expf(sc[a][0]-mx), e1 = expf(sc[a][1]-mx);
        float e2 = expf(sc[a][2]-mx), e3 = expf(sc[a][3]-mx);
        float den = e0 + e1 + e2 + e3;
        float o = (e0*v[0] + e1*v[1] + e2*v[2] + e3*v[3]) / den;
        AOh[(size_t)(s*4 + a)*256 + h*32 + lane] = __float2half_rn(o);
    }
}

// ---------------- layernorm, warp-per-token, layout remap, optional fp16 out ----------------
__global__ void ln_kernel(const float* __restrict__ X, const float* __restrict__ g,
                          const float* __restrict__ b, float* __restrict__ Y,
                          __half* __restrict__ Yh, int mode) {
    int t = blockIdx.x * 8 + (threadIdx.x >> 5);
    int lane = threadIdx.x & 31;
    const float* xr = X + (size_t)t * 256 + lane * 8;
    float4 x0 = *reinterpret_cast<const float4*>(xr);
    float4 x1 = *reinterpret_cast<const float4*>(xr + 4);
    float s = x0.x + x0.y + x0.z + x0.w + x1.x + x1.y + x1.z + x1.w;
    #pragma unroll
    for (int o = 16; o > 0; o >>= 1) s += __shfl_xor_sync(0xffffffffu, s, o);
    float m = s * (1.0f / 256.0f);
    float d[8] = {x0.x-m, x0.y-m, x0.z-m, x0.w-m, x1.x-m, x1.y-m, x1.z-m, x1.w-m};
    float vs = 0.f;
    #pragma unroll
    for (int i = 0; i < 8; i++) vs += d[i]*d[i];
    #pragma unroll
    for (int o = 16; o > 0; o >>= 1) vs += __shfl_xor_sync(0xffffffffu, vs, o);
    float inv = rsqrtf(vs * (1.0f/256.0f) + 1e-5f);
    float y[8];
    const float* gp = g + lane*8;
    const float* bp = b + lane*8;
    #pragma unroll
    for (int i = 0; i < 8; i++) y[i] = d[i]*inv*gp[i] + bp[i];
    int ot;
    if (mode == 0) ot = t;
    else if (mode == 1) { int bb = t >> 12, r = (t >> 2) & 1023, c = t & 3; ot = ((bb<<2)|c)*1024 + r; }
    else { int bf = t >> 10, r = t & 1023; int bb = bf >> 2, c = bf & 3; ot = bb*4096 + r*4 + c; }
    float* yr = Y + (size_t)ot * 256 + lane * 8;
    *reinterpret_cast<float4*>(yr)     = make_float4(y[0], y[1], y[2], y[3]);
    *reinterpret_cast<float4*>(yr + 4) = make_float4(y[4], y[5], y[6], y[7]);
    if (Yh) {
        size_t o2 = (size_t)ot * 256 + lane * 8;
        #pragma unroll
        for (int i = 0; i < 4; i++) {
            __half2 h;
            h.x = __float2half_rn(y[2*i]); h.y = __float2half_rn(y[2*i+1]);
            *reinterpret_cast<__half2*>(Yh + o2 + 2*i) = h;
        }
    }
}

// ---------------- indexer: scales / quantize / score+topk ----------------
__global__ void idx_scales(const float* __restrict__ IQK, float* __restrict__ SC) {
    int bf = blockIdx.x, h = blockIdx.y, kind = blockIdx.z;
    int r0 = (kind == 1) ? SPLIT : 0;
    int r1 = (kind == 1) ? 1024 : SPLIT;
    int cb = (kind == 2) ? 32 : 0;
    int n = (r1 - r0) * 8;
    float m = 0.0f;
    for (int i = threadIdx.x; i < n; i += 256) {
        int r = r0 + (i >> 3), d = i & 7;
        m = fmaxf(m, fabsf(IQK[(size_t)(bf*1024 + r)*64 + cb + h*8 + d]));
    }
    __shared__ float sm[8];
    #pragma unroll
    for (int o = 16; o > 0; o >>= 1) m = fmaxf(m, __shfl_xor_sync(0xffffffffu, m, o));
    if ((threadIdx.x & 31) == 0) sm[threadIdx.x >> 5] = m;
    __syncthreads();
    if (threadIdx.x == 0) {
        float mm = sm[0];
        for (int i = 1; i < 8; i++) mm = fmaxf(mm, sm[i]);
        SC[kind*32 + bf*4 + h] = (mm + 1e-6f) / 127.0f;
    }
}

__global__ void idx_quant(const float* __restrict__ IQK, const float* __restrict__ SC,
                          int* __restrict__ QI, int* __restrict__ KI) {
    int idx = blockIdx.x * 256 + threadIdx.x;
    if (idx >= NTOK*32) return;
    int t = idx >> 5, j = idx & 31, h = j >> 3;
    int bf = t >> 10, r = t & 1023;
    char* qb = (char*)QI;
    char* kb = (char*)KI;
    float qs = SC[(r < SPLIT ? 0 : 1)*32 + bf*4 + h];
    float qv = rintf(IQK[(size_t)t*64 + j] / qs);
    qv = fminf(fmaxf(qv, -127.0f), 127.0f);
    qb[idx] = (char)(int)qv;
    if (r < SPLIT) {
        float ks = SC[64 + bf*4 + h];
        float kv = rintf(IQK[(size_t)t*64 + 32 + j] / ks);
        kv = fminf(fmaxf(kv, -127.0f), 127.0f);
        kb[idx] = (char)(int)kv;
    } else {
        kb[idx] = 0;
    }
}

// warp-per-token top-k: scores in 24 regs/lane, 32 argmax rounds, no block barriers
__global__ void idx_topk(const int* __restrict__ QI, const int* __restrict__ KI,
                         const float* __restrict__ SC, const float* __restrict__ ow,
                         int* __restrict__ IDX) {
    int warp = threadIdx.x >> 5, lane = threadIdx.x & 31;
    int t = blockIdx.x * 8 + warp;
    int bf = t >> 10, r = t & 1023;

    int4 q0 = *reinterpret_cast<const int4*>(QI + (size_t)t*8);
    int4 q1 = *reinterpret_cast<const int4*>(QI + (size_t)t*8 + 4);
    int qw[8] = {q0.x, q0.y, q0.z, q0.w, q1.x, q1.y, q1.z, q1.w};

    float ssc[4], sow[4];
    #pragma unroll
    for (int h = 0; h < 4; h++) {
        float qs = SC[(r < SPLIT ? 0 : 1)*32 + bf*4 + h];
        ssc[h] = qs * SC[64 + bf*4 + h];
        sow[h] = ow[h];
    }

    float rv[24];
    #pragma unroll
    for (int i = 0; i < 24; i++) {
        int k = i*32 + lane;
        const int* kw = KI + (size_t)(bf*1024 + k)*8;
        int4 k0 = *reinterpret_cast<const int4*>(kw);
        int4 k1 = *reinterpret_cast<const int4*>(kw + 4);
        int kwv[8] = {k0.x, k0.y, k0.z, k0.w, k1.x, k1.y, k1.z, k1.w};
        float acc = 0.f;
        #pragma unroll
        for (int h = 0; h < 4; h++) {
            int d = __dp4a(qw[2*h], kwv[2*h], __dp4a(qw[2*h+1], kwv[2*h+1], 0));
            acc += fmaxf((float)d * ssc[h], 0.0f) * sow[h];
        }
        rv[i] = acc;
    }

    for (int sel = 0; sel < TOPK_; sel++) {
        float bv = -FLT_MAX; int bi = 0x7fffffff;
        #pragma unroll
        for (int i = 0; i < 24; i++) {
            if (rv[i] > bv) { bv = rv[i]; bi = i*32 + lane; }
        }
        #pragma unroll
        for (int o = 16; o > 0; o >>= 1) {
            float ov = __shfl_xor_sync(0xffffffffu, bv, o);
            int   oi = __shfl_xor_sync(0xffffffffu, bi, o);
            if (ov > bv || (ov == bv && oi < bi)) { bv = ov; bi = oi; }
        }
        if (lane == 0) IDX[t*TOPK_ + sel] = bi;
        if ((bi & 31) == lane) rv[bi >> 5] = -FLT_MAX;
    }
}

// ---------------- sparse MLA attention v2: smem-staged, shuffle-light ----------------
__global__ void mla_attn(const float* __restrict__ MQ, const float* __restrict__ KV,
                         const int* __restrict__ IDX, __half* __restrict__ AO2h) {
    __shared__ float sBuf[8][32][33];
    __shared__ float sQ[8][32];
    __shared__ float sW[8][32];
    __shared__ int sidx[32];

    int t = blockIdx.x;
    int bf = t >> 10;
    int h = threadIdx.x >> 5, lane = threadIdx.x & 31;

    if (threadIdx.x < 32) sidx[threadIdx.x] = IDX[t*TOPK_ + threadIdx.x];
    float q = MQ[(size_t)t*256 + h*32 + lane];
    sQ[h][lane] = q;
    __syncthreads();

    #pragma unroll 4
    for (int j = 0; j < 32; j++) {
        int kt = bf*1024 + sidx[j];
        sBuf[h][j][lane] = KV[(size_t)kt*512 + h*32 + lane];
    }
    __syncwarp();

    float score = 0.0f;
    #pragma unroll
    for (int d = 0; d < 32; d++)
        score += sQ[h][d] * sBuf[h][lane][d];
    score *= 0.17677669529663687f;

    float mx = score;
    #pragma unroll
    for (int o = 16; o > 0; o >>= 1) mx = fmaxf(mx, __shfl_xor_sync(0xffffffffu, mx, o));
    float e = expf(score - mx);
    float ssum = e;
    #pragma unroll
    for (int o = 16; o > 0; o >>= 1) ssum += __shfl_xor_sync(0xffffffffu, ssum, o);
    sW[h][lane] = e / ssum;
    __syncwarp();

    #pragma unroll 4
    for (int j = 0; j < 32; j++) {
        int kt = bf*1024 + sidx[j];
        sBuf[h][j][lane] = KV[(size_t)kt*512 + 256 + h*32 + lane];
    }
    __syncwarp();

    float acc = 0.0f;
    #pragma unroll
    for (int j = 0; j < 32; j++)
        acc += sW[h][j] * sBuf[h][j][lane];

    AO2h[(size_t)t*256 + h*32 + lane] = __float2half_rn(acc);
}

// ---------------- host launcher ----------------
static float* symF(const void* sym) { void* p = nullptr; cudaGetSymbolAddress(&p, sym); return (float*)p; }
static int*   symI(const void* sym) { void* p = nullptr; cudaGetSymbolAddress(&p, sym); return (int*)p; }
static __half* symH(const void* sym) { void* p = nullptr; cudaGetSymbolAddress(&p, sym); return (__half*)p; }

extern "C" void kernel_launch(void* const* d_in, const int* in_sizes, int n_in,
                              void* d_out, int out_size) {
    (void)in_sizes; (void)n_in; (void)out_size;
    const float* src      = (const float*)d_in[0];
    const float* fa_in_w  = (const float*)d_in[2];
    const float* fa_in_b  = (const float*)d_in[3];
    const float* fa_out_w = (const float*)d_in[4];
    const float* fa_out_b = (const float*)d_in[5];
    const float* n1g = (const float*)d_in[6];
    const float* n1b = (const float*)d_in[7];
    const float* iqw = (const float*)d_in[8];
    const float* ikw = (const float*)d_in[9];
    const float* iow = (const float*)d_in[10];
    const float* mqw = (const float*)d_in[11];
    const float* mdw = (const float*)d_in[12];
    const float* muw = (const float*)d_in[13];
    const float* mow = (const float*)d_in[14];
    const float* n2g = (const float*)d_in[15];
    const float* n2b = (const float*)d_in[16];
    const float* l1w = (const float*)d_in[17];
    const float* l1b = (const float*)d_in[18];
    const float* l2w = (const float*)d_in[19];
    const float* l2b = (const float*)d_in[20];
    const float* n3g = (const float*)d_in[21];
    const float* n3b = (const float*)d_in[22];

    float* QKV = symF(g_QKV); float* X   = symF(g_X);   float* ST  = symF(g_ST);
    float* IQK = symF(g_IQK); float* SC  = symF(g_SC);
    int*   QI  = symI(g_QI);  int*   KI  = symI(g_KI);  int*   IDX = symI(g_IDX);
    float* MQ  = symF(g_MQ);  float* KV  = symF(g_KV);  float* ST2 = symF(g_ST2);
    float* X2  = symF(g_X2);  float* X3  = symF(g_X3);
    __half *SRCh=symH(g_SRCh);
    __half *AOh=symH(g_AOh);
    __half *STh=symH(g_STh);
    __half *CDh=symH(g_CDh);
    __half *AO2h=symH(g_AO2h);
    __half *X2h=symH(g_X2h);
    __half *H1h=symH(g_H1h);
    __half *Wp=symH(g_W);

    static cudaStream_t sW = nullptr, sB = nullptr;
    static cudaEvent_t evRoot = nullptr, evFA = nullptr, evW = nullptr, ev1 = nullptr, evB = nullptr;
    if (!sW) {
        cudaStreamCreateWithFlags(&sW, cudaStreamNonBlocking);
        cudaStreamCreateWithFlags(&sB, cudaStreamNonBlocking);
        cudaEventCreateWithFlags(&evRoot, cudaEventDisableTiming);
        cudaEventCreateWithFlags(&evFA,  cudaEventDisableTiming);
        cudaEventCreateWithFlags(&evW,   cudaEventDisableTiming);
        cudaEventCreateWithFlags(&ev1,   cudaEventDisableTiming);
        cudaEventCreateWithFlags(&evB,   cudaEventDisableTiming);
        cudaFuncSetAttribute(hgemm<0,0>, cudaFuncAttributeMaxDynamicSharedMemorySize, SMEMTOT);
        cudaFuncSetAttribute(hgemm<1,0>, cudaFuncAttributeMaxDynamicSharedMemorySize, SMEMTOT);
        cudaFuncSetAttribute(hgemm<2,1>, cudaFuncAttributeMaxDynamicSharedMemorySize, SMEMTOT);
        cudaFuncSetAttribute(hgemm<3,0>, cudaFuncAttributeMaxDynamicSharedMemorySize, SMEMTOT);
    }

    dim3 blk(256);

    // Fork: weight conversions on side stream, overlapping src conversion / Stage A
    cudaEventRecord(evRoot, 0);
    cudaStreamWaitEvent(sW, evRoot, 0);
    wcvt_fa<<<256, blk, 0, sW>>>(fa_in_w, fa_out_w, Wp);
    cudaEventRecord(evFA, sW);
    wcvt6<<<752, blk, 0, sW>>>(mqw, mdw, muw, mow, l1w, l2w, iqw, ikw, Wp);
    cudaEventRecord(evW, sW);

    // Stage A (main stream)
    cvt_h<<<2048, blk>>>(src, SRCh, NTOK*256);
    cudaStreamWaitEvent(0, evFA, 0);
    hgemm<0,0><<<dim3(12,64), blk, SMEMTOT>>>(SRCh, Wp+W_FAIN,
        fa_in_b, nullptr, QKV, nullptr, nullptr, NTOK, 768, 256);
    feat_attn<<<2048, blk>>>(QKV, AOh);
    hgemm<1,0><<<dim3(4,64), blk, SMEMTOT>>>(AOh, Wp+W_FAOUT,
        fa_out_b, src, X, nullptr, nullptr, NTOK, 256, 256);
    ln_kernel<<<NTOK/8, blk>>>(X, n1g, n1b, ST, STh, 1);

    // Merged MQ(fp32) + MD(fp16) + IDX(fp32) GEMM, N=448
    cudaStreamWaitEvent(0, evW, 0);
    hgemm<3,0><<<dim3(7,64), blk, SMEMTOT>>>(STh, Wp+W_MQ,
        nullptr, nullptr, MQ, CDh, IQK, NTOK, 448, 256);

    // Fork indexer branch (scales/quant/topk)
    cudaEventRecord(ev1, 0);
    cudaStreamWaitEvent(sB, ev1, 0);
    idx_scales<<<dim3(8,4,3), blk, 0, sB>>>(IQK, SC);
    idx_quant<<<NTOK*32/256, blk, 0, sB>>>(IQK, SC, QI, KI);
    idx_topk<<<NTOK/8, blk, 0, sB>>>(QI, KI, SC, iow, IDX);
    cudaEventRecord(evB, sB);

    // Stage C (main, concurrent with indexer branch)
    hgemm<0,0><<<dim3(8,64), blk, SMEMTOT>>>(CDh, Wp+W_MU,
        nullptr, nullptr, KV, nullptr, nullptr, NTOK, 512, 128);

    // Join + attention
    cudaStreamWaitEvent(0, evB, 0);
    mla_attn<<<NTOK, blk>>>(MQ, KV, IDX, AO2h);
    hgemm<1,0><<<dim3(4,64), blk, SMEMTOT>>>(AO2h, Wp+W_MO,
        nullptr, ST, ST2, nullptr, nullptr, NTOK, 256, 256);

    // Stage D
    ln_kernel<<<NTOK/8, blk>>>(ST2, n2g, n2b, X2, X2h, 2);
    hgemm<2,1><<<dim3(16,64), blk, SMEMTOT>>>(X2h, Wp+W_L1,
        l1b, nullptr, nullptr, H1h, nullptr, NTOK, 1024, 256);
    hgemm<1,0><<<dim3(4,64), blk, SMEMTOT>>>(H1h, Wp+W_L2,
        l2b, X2, X3, nullptr, nullptr, NTOK, 256, 1024);
    ln_kernel<<<NTOK/8, blk>>>(X3, n3g, n3b, (float*)d_out, nullptr, 0);
}